// round 1
// baseline (speedup 1.0000x reference)
#include <cuda_runtime.h>
#include <math.h>

#define S_LEN 2048
#define HID   2048
#define NHQ   16
#define NKV   4
#define HD    128
#define WIN   1024

// Scratch (no cudaMalloc allowed)
__device__ float g_q[S_LEN * NHQ * HD];     // (S, 16*128) = (2048, 2048)
__device__ float g_k[S_LEN * NKV * HD];     // (2048, 512)
__device__ float g_v[S_LEN * NKV * HD];     // (2048, 512)
__device__ float g_attn[S_LEN * NHQ * HD];  // (2048, 2048)

// ---------------------------------------------------------------------------
// Classic 128x128 register-tiled SGEMM: C[M,N] = A[M,K] @ B[K,N], row-major.
// M,N,K multiples of 128/16. 256 threads, 8x8 per-thread tile.
// ---------------------------------------------------------------------------
__global__ __launch_bounds__(256) void sgemm128(const float* __restrict__ A,
                                                const float* __restrict__ B,
                                                float* __restrict__ C,
                                                int M, int N, int K) {
    __shared__ float As[16 * 128];   // [k][m] (transposed store)
    __shared__ float Bs[16 * 128];   // [k][n]

    const int tid  = threadIdx.x;
    const int tx   = tid & 15;
    const int ty   = tid >> 4;
    const int brow = blockIdx.y * 128;
    const int bcol = blockIdx.x * 128;

    // A-tile load mapping: 128x16 = 512 float4, 2 per thread
    const int arow = tid >> 2;          // 0..63
    const int acol = (tid & 3) * 4;     // 0,4,8,12
    // B-tile load mapping: 16x128 = 512 float4, 2 per thread
    const int brB  = tid >> 5;          // 0..7
    const int bcB  = (tid & 31) * 4;    // 0..124

    float acc[8][8];
#pragma unroll
    for (int i = 0; i < 8; ++i)
#pragma unroll
        for (int j = 0; j < 8; ++j) acc[i][j] = 0.f;

    for (int kt = 0; kt < K; kt += 16) {
#pragma unroll
        for (int r = 0; r < 2; ++r) {
            float4 av = *reinterpret_cast<const float4*>(
                &A[(size_t)(brow + arow + r * 64) * K + kt + acol]);
            As[(acol + 0) * 128 + arow + r * 64] = av.x;
            As[(acol + 1) * 128 + arow + r * 64] = av.y;
            As[(acol + 2) * 128 + arow + r * 64] = av.z;
            As[(acol + 3) * 128 + arow + r * 64] = av.w;
        }
#pragma unroll
        for (int r = 0; r < 2; ++r) {
            float4 bv = *reinterpret_cast<const float4*>(
                &B[(size_t)(kt + brB + r * 8) * N + bcol + bcB]);
            *reinterpret_cast<float4*>(&Bs[(brB + r * 8) * 128 + bcB]) = bv;
        }
        __syncthreads();

#pragma unroll
        for (int k = 0; k < 16; ++k) {
            float af[8], bf[8];
            float4 a0 = *reinterpret_cast<const float4*>(&As[k * 128 + ty * 8]);
            float4 a1 = *reinterpret_cast<const float4*>(&As[k * 128 + ty * 8 + 4]);
            float4 b0 = *reinterpret_cast<const float4*>(&Bs[k * 128 + tx * 8]);
            float4 b1 = *reinterpret_cast<const float4*>(&Bs[k * 128 + tx * 8 + 4]);
            af[0]=a0.x; af[1]=a0.y; af[2]=a0.z; af[3]=a0.w;
            af[4]=a1.x; af[5]=a1.y; af[6]=a1.z; af[7]=a1.w;
            bf[0]=b0.x; bf[1]=b0.y; bf[2]=b0.z; bf[3]=b0.w;
            bf[4]=b1.x; bf[5]=b1.y; bf[6]=b1.z; bf[7]=b1.w;
#pragma unroll
            for (int i = 0; i < 8; ++i)
#pragma unroll
                for (int j = 0; j < 8; ++j)
                    acc[i][j] = fmaf(af[i], bf[j], acc[i][j]);
        }
        __syncthreads();
    }

#pragma unroll
    for (int i = 0; i < 8; ++i) {
        float4 c0 = make_float4(acc[i][0], acc[i][1], acc[i][2], acc[i][3]);
        float4 c1 = make_float4(acc[i][4], acc[i][5], acc[i][6], acc[i][7]);
        size_t off = (size_t)(brow + ty * 8 + i) * N + bcol + tx * 8;
        *reinterpret_cast<float4*>(&C[off])     = c0;
        *reinterpret_cast<float4*>(&C[off + 4]) = c1;
    }
}

// ---------------------------------------------------------------------------
// RoPE (interleaved pairs) applied in-place to q and k.
// ---------------------------------------------------------------------------
__global__ void rope_kernel(const float* __restrict__ fc,
                            const int* __restrict__ pos) {
    int idx = blockIdx.x * blockDim.x + threadIdx.x;
    const int NQ = S_LEN * NHQ * (HD / 2);
    const int NK = S_LEN * NKV * (HD / 2);
    if (idx < NQ) {
        int d = idx & 63;
        int rest = idx >> 6;
        int h = rest & (NHQ - 1);
        int s = rest >> 4;
        int p = pos[s];
        float c  = fc[p * HD + d * 2];
        float sn = fc[p * HD + d * 2 + 1];
        float* ptr = g_q + ((size_t)s * (NHQ * HD) + h * HD + d * 2);
        float a = ptr[0], b = ptr[1];
        ptr[0] = a * c - b * sn;
        ptr[1] = a * sn + b * c;
    } else if (idx < NQ + NK) {
        int j = idx - NQ;
        int d = j & 63;
        int rest = j >> 6;
        int h = rest & (NKV - 1);
        int s = rest >> 2;
        int p = pos[s];
        float c  = fc[p * HD + d * 2];
        float sn = fc[p * HD + d * 2 + 1];
        float* ptr = g_k + ((size_t)s * (NKV * HD) + h * HD + d * 2);
        float a = ptr[0], b = ptr[1];
        ptr[0] = a * c - b * sn;
        ptr[1] = a * sn + b * c;
    }
}

// ---------------------------------------------------------------------------
// Flash attention with sliding window (1024), GQA 16->4 heads.
// grid (NHQ, S/64), 256 threads. Thread (ty 0..15, tx 0..15):
//   scores:  q-rows ty*4+j (j<4), k-cols i*16+tx (i<4)
//   output:  q-rows ty*4+j,      d-cols c*16+tx (c<8)
// ---------------------------------------------------------------------------
#define QSTR 129
#define PSTR 68
__global__ __launch_bounds__(256) void attn_kernel(float* __restrict__ out) {
    extern __shared__ float sm[];
    float* Qs = sm;                      // 64 x QSTR
    float* Ks = Qs + 64 * QSTR;          // 64 x QSTR
    float* Vs = Ks + 64 * QSTR;          // 64 x QSTR
    float* Ps = Vs + 64 * QSTR;          // 64 x PSTR

    const int h   = blockIdx.x;
    const int q0  = blockIdx.y * 64;
    const int kvh = h >> 2;              // h / N_REP
    const int tid = threadIdx.x;
    const int tx  = tid & 15;
    const int ty  = tid >> 4;
    const float scale = 0.08838834764831845f;  // 1/sqrt(128)
    const float NEG = -1e30f;

    // Load Q tile
    for (int idx = tid; idx < 64 * 128; idx += 256) {
        int r = idx >> 7, d = idx & 127;
        Qs[r * QSTR + d] = g_q[(size_t)(q0 + r) * (NHQ * HD) + h * HD + d];
    }

    float m[4], l[4], acc[4][8];
#pragma unroll
    for (int j = 0; j < 4; ++j) {
        m[j] = NEG; l[j] = 0.f;
#pragma unroll
        for (int c = 0; c < 8; ++c) acc[j][c] = 0.f;
    }

    int lo_t = q0 - (WIN - 1); if (lo_t < 0) lo_t = 0;
    const int kb_lo = lo_t >> 6;
    const int kb_hi = q0 >> 6;

    __syncthreads();

    for (int kb = kb_lo; kb <= kb_hi; ++kb) {
        const int t0 = kb * 64;
        for (int idx = tid; idx < 64 * 128; idx += 256) {
            int r = idx >> 7, d = idx & 127;
            size_t g = (size_t)(t0 + r) * (NKV * HD) + kvh * HD + d;
            Ks[r * QSTR + d] = g_k[g];
            Vs[r * QSTR + d] = g_v[g];
        }
        __syncthreads();

        // ---- scores ----
        float s[4][4];
#pragma unroll
        for (int j = 0; j < 4; ++j)
#pragma unroll
            for (int i = 0; i < 4; ++i) s[j][i] = 0.f;

#pragma unroll 4
        for (int kk = 0; kk < 128; ++kk) {
            float qf[4], kf[4];
#pragma unroll
            for (int j = 0; j < 4; ++j) qf[j] = Qs[(ty * 4 + j) * QSTR + kk];
#pragma unroll
            for (int i = 0; i < 4; ++i) kf[i] = Ks[(i * 16 + tx) * QSTR + kk];
#pragma unroll
            for (int j = 0; j < 4; ++j)
#pragma unroll
                for (int i = 0; i < 4; ++i)
                    s[j][i] = fmaf(qf[j], kf[i], s[j][i]);
        }

        // mask + scale
#pragma unroll
        for (int j = 0; j < 4; ++j) {
            int qg = q0 + ty * 4 + j;
#pragma unroll
            for (int i = 0; i < 4; ++i) {
                int t = t0 + i * 16 + tx;
                bool ok = (t <= qg) && (qg - t < WIN);
                s[j][i] = ok ? s[j][i] * scale : NEG;
            }
        }

        // ---- online softmax ----
#pragma unroll
        for (int j = 0; j < 4; ++j) {
            float mt = fmaxf(fmaxf(s[j][0], s[j][1]), fmaxf(s[j][2], s[j][3]));
#pragma unroll
            for (int off = 8; off >= 1; off >>= 1)
                mt = fmaxf(mt, __shfl_xor_sync(0xffffffffu, mt, off, 16));
            float mnew = fmaxf(m[j], mt);
            float esc  = __expf(m[j] - mnew);
            float rs = 0.f;
#pragma unroll
            for (int i = 0; i < 4; ++i) {
                float p = __expf(s[j][i] - mnew);
                Ps[(ty * 4 + j) * PSTR + i * 16 + tx] = p;
                rs += p;
            }
#pragma unroll
            for (int off = 8; off >= 1; off >>= 1)
                rs += __shfl_xor_sync(0xffffffffu, rs, off, 16);
            l[j] = l[j] * esc + rs;
            m[j] = mnew;
#pragma unroll
            for (int c = 0; c < 8; ++c) acc[j][c] *= esc;
        }
        __syncwarp(0xffffffffu);  // Ps rows are produced within the same warp

        // ---- P @ V ----
#pragma unroll 2
        for (int kk = 0; kk < 64; ++kk) {
            float vv[8];
#pragma unroll
            for (int c = 0; c < 8; ++c) vv[c] = Vs[kk * QSTR + c * 16 + tx];
#pragma unroll
            for (int j = 0; j < 4; ++j) {
                float p = Ps[(ty * 4 + j) * PSTR + kk];
#pragma unroll
                for (int c = 0; c < 8; ++c)
                    acc[j][c] = fmaf(p, vv[c], acc[j][c]);
            }
        }
        __syncthreads();  // protect Ks/Vs before next tile load
    }

    // epilogue: normalize, write (S, NH*HD)
#pragma unroll
    for (int j = 0; j < 4; ++j) {
        float inv = 1.f / l[j];
        int qg = q0 + ty * 4 + j;
#pragma unroll
        for (int c = 0; c < 8; ++c)
            out[(size_t)qg * (NHQ * HD) + h * HD + c * 16 + tx] = acc[j][c] * inv;
    }
}

// ---------------------------------------------------------------------------
extern "C" void kernel_launch(void* const* d_in, const int* in_sizes, int n_in,
                              void* d_out, int out_size) {
    const float* hs = (const float*)d_in[0];
    const float* fc = (const float*)d_in[1];
    // d_in[2] attention_mask (all true), d_in[3] causal_mask: computed analytically
    const int*   pos = (const int*)d_in[4];
    const float* Wq = (const float*)d_in[5];
    const float* Wk = (const float*)d_in[6];
    const float* Wv = (const float*)d_in[7];
    const float* Wo = (const float*)d_in[8];
    float* out = (float*)d_out;

    float *qp, *kp, *vp, *ap;
    cudaGetSymbolAddress((void**)&qp, g_q);
    cudaGetSymbolAddress((void**)&kp, g_k);
    cudaGetSymbolAddress((void**)&vp, g_v);
    cudaGetSymbolAddress((void**)&ap, g_attn);

    // QKV projections
    sgemm128<<<dim3(HID / 128, S_LEN / 128), 256>>>(hs, Wq, qp, S_LEN, NHQ * HD, HID);
    sgemm128<<<dim3((NKV * HD) / 128, S_LEN / 128), 256>>>(hs, Wk, kp, S_LEN, NKV * HD, HID);
    sgemm128<<<dim3((NKV * HD) / 128, S_LEN / 128), 256>>>(hs, Wv, vp, S_LEN, NKV * HD, HID);

    // RoPE
    {
        int total = S_LEN * NHQ * (HD / 2) + S_LEN * NKV * (HD / 2);
        rope_kernel<<<(total + 255) / 256, 256>>>(fc, pos);
    }

    // Attention
    {
        int smem = (3 * 64 * QSTR + 64 * PSTR) * (int)sizeof(float);
        cudaFuncSetAttribute(attn_kernel, cudaFuncAttributeMaxDynamicSharedMemorySize, smem);
        attn_kernel<<<dim3(NHQ, S_LEN / 64), 256, smem>>>(ap);
    }

    // Output projection
    sgemm128<<<dim3(HID / 128, S_LEN / 128), 256>>>(ap, Wo, out, S_LEN, HID, HID);
}

// round 4
// speedup vs baseline: 1.4416x; 1.4416x over previous
#include <cuda_runtime.h>
#include <cstdint>
#include <math.h>

#define S_LEN 2048
#define HID   2048
#define NHQ   16
#define NKV   4
#define HD    128
#define WIN   1024

// ---------------- scratch (no cudaMalloc allowed) ----------------
__device__ float g_q[S_LEN * NHQ * HD];
__device__ float g_k[S_LEN * NKV * HD];
__device__ float g_v[S_LEN * NKV * HD];
__device__ float g_attn[S_LEN * NHQ * HD];

__device__ __forceinline__ uint32_t f2tf32(float x) {
    uint32_t r; asm("cvt.rna.tf32.f32 %0, %1;" : "=r"(r) : "f"(x)); return r;
}
__device__ __forceinline__ void mma_tf32(float c[4], const uint32_t a[4], const uint32_t b[2]) {
    asm volatile("mma.sync.aligned.m16n8k8.row.col.f32.tf32.tf32.f32 "
        "{%0,%1,%2,%3}, {%4,%5,%6,%7}, {%8,%9}, {%0,%1,%2,%3};"
        : "+f"(c[0]), "+f"(c[1]), "+f"(c[2]), "+f"(c[3])
        : "r"(a[0]), "r"(a[1]), "r"(a[2]), "r"(a[3]), "r"(b[0]), "r"(b[1]));
}

// ---------------------------------------------------------------------------
// TF32 warp-mma GEMM: C[M,N] = A[M,K] @ W[K,N], all row-major.
// CTA 128x128, K-tile 32, 8 warps (2x4), warp tile 64x32, double-buffered.
// M%128==0, N%128==0, K%32==0.
// ---------------------------------------------------------------------------
#define ASTR 36
#define BSTR 132
#define A_ELEMS (128 * ASTR)          // 4608 floats
#define B_ELEMS (32 * BSTR)           // 4224 floats
#define GEMM_SMEM (2 * (A_ELEMS + B_ELEMS) * 4)   // 70656 B

__global__ __launch_bounds__(256, 1) void gemm_mma(const float* __restrict__ A,
                                                   const float* __restrict__ W,
                                                   float* __restrict__ C,
                                                   int M, int N, int K) {
    extern __shared__ float smg[];
    float* Abuf[2] = { smg, smg + A_ELEMS };
    float* Bbuf[2] = { smg + 2 * A_ELEMS, smg + 2 * A_ELEMS + B_ELEMS };

    const int tid  = threadIdx.x;
    const int lane = tid & 31;
    const int wid  = tid >> 5;
    const int wm   = wid & 1;          // 0..1 -> 64-row slab
    const int wn   = wid >> 1;         // 0..3 -> 32-col slab
    const int g    = lane >> 2;
    const int tig  = lane & 3;
    const int brow = blockIdx.y * 128;
    const int bcol = blockIdx.x * 128;

    // LDG mappings
    const int arow = (tid * 4) >> 5 << 2;            // unused helper removed below
    (void)arow;

    float acc[4][4][4];
#pragma unroll
    for (int mi = 0; mi < 4; ++mi)
#pragma unroll
        for (int ni = 0; ni < 4; ++ni)
#pragma unroll
            for (int f = 0; f < 4; ++f) acc[mi][ni][f] = 0.f;

    // ---- preload K-tile 0 ----
    {
#pragma unroll
        for (int i = 0; i < 4; ++i) {
            int idx = i * 256 + tid;
            int r = idx >> 3, c = (idx & 7) * 4;
            float4 v = *reinterpret_cast<const float4*>(&A[(size_t)(brow + r) * K + c]);
            uint4 t = { f2tf32(v.x), f2tf32(v.y), f2tf32(v.z), f2tf32(v.w) };
            *reinterpret_cast<uint4*>(&Abuf[0][r * ASTR + c]) = t;
        }
#pragma unroll
        for (int i = 0; i < 4; ++i) {
            int idx = i * 256 + tid;
            int r = idx >> 5, c = (idx & 31) * 4;
            float4 v = *reinterpret_cast<const float4*>(&W[(size_t)r * N + bcol + c]);
            uint4 t = { f2tf32(v.x), f2tf32(v.y), f2tf32(v.z), f2tf32(v.w) };
            *reinterpret_cast<uint4*>(&Bbuf[0][r * BSTR + c]) = t;
        }
    }
    __syncthreads();

    const int iters = K / 32;
    for (int kt = 0; kt < iters; ++kt) {
        const int buf = kt & 1;
        const bool has_next = (kt + 1 < iters);
        float4 aR[4], bR[4];
        if (has_next) {
            const int k0 = (kt + 1) * 32;
#pragma unroll
            for (int i = 0; i < 4; ++i) {
                int idx = i * 256 + tid;
                int r = idx >> 3, c = (idx & 7) * 4;
                aR[i] = *reinterpret_cast<const float4*>(&A[(size_t)(brow + r) * K + k0 + c]);
            }
#pragma unroll
            for (int i = 0; i < 4; ++i) {
                int idx = i * 256 + tid;
                int r = idx >> 5, c = (idx & 31) * 4;
                bR[i] = *reinterpret_cast<const float4*>(&W[(size_t)(k0 + r) * N + bcol + c]);
            }
        }

        const float* As = Abuf[buf];
        const float* Bs = Bbuf[buf];
#pragma unroll
        for (int kk = 0; kk < 4; ++kk) {
            const int kb = kk * 8;
            uint32_t af[4][4], bf[4][2];
#pragma unroll
            for (int mi = 0; mi < 4; ++mi) {
                int r0 = wm * 64 + mi * 16 + g;
                af[mi][0] = __float_as_uint(As[r0 * ASTR + kb + tig]);
                af[mi][1] = __float_as_uint(As[(r0 + 8) * ASTR + kb + tig]);
                af[mi][2] = __float_as_uint(As[r0 * ASTR + kb + tig + 4]);
                af[mi][3] = __float_as_uint(As[(r0 + 8) * ASTR + kb + tig + 4]);
            }
#pragma unroll
            for (int ni = 0; ni < 4; ++ni) {
                int c0 = wn * 32 + ni * 8 + g;
                bf[ni][0] = __float_as_uint(Bs[(kb + tig) * BSTR + c0]);
                bf[ni][1] = __float_as_uint(Bs[(kb + tig + 4) * BSTR + c0]);
            }
#pragma unroll
            for (int mi = 0; mi < 4; ++mi)
#pragma unroll
                for (int ni = 0; ni < 4; ++ni)
                    mma_tf32(acc[mi][ni], af[mi], bf[ni]);
        }

        if (has_next) {
            const int nb = buf ^ 1;
#pragma unroll
            for (int i = 0; i < 4; ++i) {
                int idx = i * 256 + tid;
                int r = idx >> 3, c = (idx & 7) * 4;
                uint4 t = { f2tf32(aR[i].x), f2tf32(aR[i].y), f2tf32(aR[i].z), f2tf32(aR[i].w) };
                *reinterpret_cast<uint4*>(&Abuf[nb][r * ASTR + c]) = t;
            }
#pragma unroll
            for (int i = 0; i < 4; ++i) {
                int idx = i * 256 + tid;
                int r = idx >> 5, c = (idx & 31) * 4;
                uint4 t = { f2tf32(bR[i].x), f2tf32(bR[i].y), f2tf32(bR[i].z), f2tf32(bR[i].w) };
                *reinterpret_cast<uint4*>(&Bbuf[nb][r * BSTR + c]) = t;
            }
        }
        __syncthreads();
    }

    // epilogue
#pragma unroll
    for (int mi = 0; mi < 4; ++mi) {
        int r0 = brow + wm * 64 + mi * 16 + g;
#pragma unroll
        for (int ni = 0; ni < 4; ++ni) {
            int c0 = bcol + wn * 32 + ni * 8 + 2 * tig;
            float2 v0 = make_float2(acc[mi][ni][0], acc[mi][ni][1]);
            float2 v1 = make_float2(acc[mi][ni][2], acc[mi][ni][3]);
            *reinterpret_cast<float2*>(&C[(size_t)r0 * N + c0])       = v0;
            *reinterpret_cast<float2*>(&C[(size_t)(r0 + 8) * N + c0]) = v1;
        }
    }
}

// ---------------------------------------------------------------------------
// RoPE (interleaved pairs) in-place on q and k.
// ---------------------------------------------------------------------------
__global__ void rope_kernel(const float* __restrict__ fc, const int* __restrict__ pos) {
    int idx = blockIdx.x * blockDim.x + threadIdx.x;
    const int NQ = S_LEN * NHQ * (HD / 2);
    const int NK = S_LEN * NKV * (HD / 2);
    if (idx < NQ) {
        int d = idx & 63, rest = idx >> 6;
        int h = rest & (NHQ - 1), s = rest >> 4;
        int p = pos[s];
        float c = fc[p * HD + d * 2], sn = fc[p * HD + d * 2 + 1];
        float* ptr = g_q + ((size_t)s * (NHQ * HD) + h * HD + d * 2);
        float a = ptr[0], b = ptr[1];
        ptr[0] = a * c - b * sn;
        ptr[1] = a * sn + b * c;
    } else if (idx < NQ + NK) {
        int j = idx - NQ;
        int d = j & 63, rest = j >> 6;
        int h = rest & (NKV - 1), s = rest >> 2;
        int p = pos[s];
        float c = fc[p * HD + d * 2], sn = fc[p * HD + d * 2 + 1];
        float* ptr = g_k + ((size_t)s * (NKV * HD) + h * HD + d * 2);
        float a = ptr[0], b = ptr[1];
        ptr[0] = a * c - b * sn;
        ptr[1] = a * sn + b * c;
    }
}

// ---------------------------------------------------------------------------
// Flash attention, sliding window 1024, GQA 16->4 (R1-passing version).
// ---------------------------------------------------------------------------
#define QSTR 129
#define PSTR 68
__global__ __launch_bounds__(256) void attn_kernel(float* __restrict__ out) {
    extern __shared__ float smf[];
    float* Qs = smf;
    float* Ks = Qs + 64 * QSTR;
    float* Vs = Ks + 64 * QSTR;
    float* Ps = Vs + 64 * QSTR;

    const int h = blockIdx.x;
    const int q0 = blockIdx.y * 64;
    const int kvh = h >> 2;
    const int tid = threadIdx.x;
    const int tx = tid & 15, ty = tid >> 4;
    const float scale = 0.08838834764831845f;
    const float NEG = -1e30f;

    for (int idx = tid; idx < 64 * 128; idx += 256) {
        int r = idx >> 7, d = idx & 127;
        Qs[r * QSTR + d] = g_q[(size_t)(q0 + r) * (NHQ * HD) + h * HD + d];
    }

    float m[4], l[4], acc[4][8];
#pragma unroll
    for (int j = 0; j < 4; ++j) {
        m[j] = NEG; l[j] = 0.f;
#pragma unroll
        for (int c = 0; c < 8; ++c) acc[j][c] = 0.f;
    }

    int lo_t = q0 - (WIN - 1); if (lo_t < 0) lo_t = 0;
    const int kb_lo = lo_t >> 6, kb_hi = q0 >> 6;
    __syncthreads();

    for (int kb = kb_lo; kb <= kb_hi; ++kb) {
        const int t0 = kb * 64;
        for (int idx = tid; idx < 64 * 128; idx += 256) {
            int r = idx >> 7, d = idx & 127;
            size_t gaddr = (size_t)(t0 + r) * (NKV * HD) + kvh * HD + d;
            Ks[r * QSTR + d] = g_k[gaddr];
            Vs[r * QSTR + d] = g_v[gaddr];
        }
        __syncthreads();

        float s[4][4];
#pragma unroll
        for (int j = 0; j < 4; ++j)
#pragma unroll
            for (int i = 0; i < 4; ++i) s[j][i] = 0.f;

#pragma unroll 4
        for (int kk = 0; kk < 128; ++kk) {
            float qf[4], kf[4];
#pragma unroll
            for (int j = 0; j < 4; ++j) qf[j] = Qs[(ty * 4 + j) * QSTR + kk];
#pragma unroll
            for (int i = 0; i < 4; ++i) kf[i] = Ks[(i * 16 + tx) * QSTR + kk];
#pragma unroll
            for (int j = 0; j < 4; ++j)
#pragma unroll
                for (int i = 0; i < 4; ++i)
                    s[j][i] = fmaf(qf[j], kf[i], s[j][i]);
        }

#pragma unroll
        for (int j = 0; j < 4; ++j) {
            int qg = q0 + ty * 4 + j;
#pragma unroll
            for (int i = 0; i < 4; ++i) {
                int t = t0 + i * 16 + tx;
                bool ok = (t <= qg) && (qg - t < WIN);
                s[j][i] = ok ? s[j][i] * scale : NEG;
            }
        }

#pragma unroll
        for (int j = 0; j < 4; ++j) {
            float mt = fmaxf(fmaxf(s[j][0], s[j][1]), fmaxf(s[j][2], s[j][3]));
#pragma unroll
            for (int off = 8; off >= 1; off >>= 1)
                mt = fmaxf(mt, __shfl_xor_sync(0xffffffffu, mt, off, 16));
            float mnew = fmaxf(m[j], mt);
            float esc = __expf(m[j] - mnew);
            float rs = 0.f;
#pragma unroll
            for (int i = 0; i < 4; ++i) {
                float p = __expf(s[j][i] - mnew);
                Ps[(ty * 4 + j) * PSTR + i * 16 + tx] = p;
                rs += p;
            }
#pragma unroll
            for (int off = 8; off >= 1; off >>= 1)
                rs += __shfl_xor_sync(0xffffffffu, rs, off, 16);
            l[j] = l[j] * esc + rs;
            m[j] = mnew;
#pragma unroll
            for (int c = 0; c < 8; ++c) acc[j][c] *= esc;
        }
        __syncwarp(0xffffffffu);

#pragma unroll 2
        for (int kk = 0; kk < 64; ++kk) {
            float vv[8];
#pragma unroll
            for (int c = 0; c < 8; ++c) vv[c] = Vs[kk * QSTR + c * 16 + tx];
#pragma unroll
            for (int j = 0; j < 4; ++j) {
                float p = Ps[(ty * 4 + j) * PSTR + kk];
#pragma unroll
                for (int c = 0; c < 8; ++c)
                    acc[j][c] = fmaf(p, vv[c], acc[j][c]);
            }
        }
        __syncthreads();
    }

#pragma unroll
    for (int j = 0; j < 4; ++j) {
        float inv = 1.f / l[j];
        int qg = q0 + ty * 4 + j;
#pragma unroll
        for (int c = 0; c < 8; ++c)
            out[(size_t)qg * (NHQ * HD) + h * HD + c * 16 + tx] = acc[j][c] * inv;
    }
}

// ---------------------------------------------------------------------------
extern "C" void kernel_launch(void* const* d_in, const int* in_sizes, int n_in,
                              void* d_out, int out_size) {
    const float* hs  = (const float*)d_in[0];
    const float* fc  = (const float*)d_in[1];
    const int*   pos = (const int*)d_in[4];
    const float* Wq  = (const float*)d_in[5];
    const float* Wk  = (const float*)d_in[6];
    const float* Wv  = (const float*)d_in[7];
    const float* Wo  = (const float*)d_in[8];
    float* out = (float*)d_out;

    float *qp, *kp, *vp, *ap;
    cudaGetSymbolAddress((void**)&qp, g_q);
    cudaGetSymbolAddress((void**)&kp, g_k);
    cudaGetSymbolAddress((void**)&vp, g_v);
    cudaGetSymbolAddress((void**)&ap, g_attn);

    cudaFuncSetAttribute(gemm_mma, cudaFuncAttributeMaxDynamicSharedMemorySize, GEMM_SMEM);

    // QKV projections (warp-mma tf32, weights consumed natively [K][N])
    gemm_mma<<<dim3((NHQ * HD) / 128, S_LEN / 128), 256, GEMM_SMEM>>>(hs, Wq, qp, S_LEN, NHQ * HD, HID);
    gemm_mma<<<dim3((NKV * HD) / 128, S_LEN / 128), 256, GEMM_SMEM>>>(hs, Wk, kp, S_LEN, NKV * HD, HID);
    gemm_mma<<<dim3((NKV * HD) / 128, S_LEN / 128), 256, GEMM_SMEM>>>(hs, Wv, vp, S_LEN, NKV * HD, HID);

    // RoPE
    {
        int total = S_LEN * NHQ * (HD / 2) + S_LEN * NKV * (HD / 2);
        rope_kernel<<<(total + 255) / 256, 256>>>(fc, pos);
    }

    // Attention (fp32 flash)
    {
        int smem = (3 * 64 * QSTR + 64 * PSTR) * (int)sizeof(float);
        cudaFuncSetAttribute(attn_kernel, cudaFuncAttributeMaxDynamicSharedMemorySize, smem);
        attn_kernel<<<dim3(NHQ, S_LEN / 64), 256, smem>>>(ap);
    }

    // Output projection
    gemm_mma<<<dim3(HID / 128, S_LEN / 128), 256, GEMM_SMEM>>>(ap, Wo, out, S_LEN, HID, HID);
}

// round 5
// speedup vs baseline: 2.0847x; 1.4461x over previous
#include <cuda_runtime.h>
#include <cstdint>
#include <math.h>

#define S_LEN 2048
#define HID   2048
#define NHQ   16
#define NKV   4
#define HD    128
#define WIN   1024

// ---------------- scratch (no cudaMalloc allowed) ----------------
__device__ float g_q[S_LEN * NHQ * HD];
__device__ float g_k[S_LEN * NKV * HD];
__device__ float g_v[S_LEN * NKV * HD];
__device__ float g_attn[S_LEN * NHQ * HD];

__device__ __forceinline__ uint32_t f2tf32(float x) {
    uint32_t r; asm("cvt.rna.tf32.f32 %0, %1;" : "=r"(r) : "f"(x)); return r;
}
__device__ __forceinline__ void mma_tf32(float c[4], const uint32_t a[4], const uint32_t b[2]) {
    asm volatile("mma.sync.aligned.m16n8k8.row.col.f32.tf32.tf32.f32 "
        "{%0,%1,%2,%3}, {%4,%5,%6,%7}, {%8,%9}, {%0,%1,%2,%3};"
        : "+f"(c[0]), "+f"(c[1]), "+f"(c[2]), "+f"(c[3])
        : "r"(a[0]), "r"(a[1]), "r"(a[2]), "r"(a[3]), "r"(b[0]), "r"(b[1]));
}

// ---------------------------------------------------------------------------
// TF32 warp-mma GEMM: C[M,N] = A[M,K] @ W[K,N], all row-major. (R4, passing)
// ---------------------------------------------------------------------------
#define ASTR 36
#define BSTR 132
#define A_ELEMS (128 * ASTR)
#define B_ELEMS (32 * BSTR)
#define GEMM_SMEM (2 * (A_ELEMS + B_ELEMS) * 4)

__global__ __launch_bounds__(256, 1) void gemm_mma(const float* __restrict__ A,
                                                   const float* __restrict__ W,
                                                   float* __restrict__ C,
                                                   int M, int N, int K) {
    extern __shared__ float smg[];
    float* Abuf[2] = { smg, smg + A_ELEMS };
    float* Bbuf[2] = { smg + 2 * A_ELEMS, smg + 2 * A_ELEMS + B_ELEMS };

    const int tid  = threadIdx.x;
    const int lane = tid & 31;
    const int wid  = tid >> 5;
    const int wm   = wid & 1;
    const int wn   = wid >> 1;
    const int g    = lane >> 2;
    const int tig  = lane & 3;
    const int brow = blockIdx.y * 128;
    const int bcol = blockIdx.x * 128;

    float acc[4][4][4];
#pragma unroll
    for (int mi = 0; mi < 4; ++mi)
#pragma unroll
        for (int ni = 0; ni < 4; ++ni)
#pragma unroll
            for (int f = 0; f < 4; ++f) acc[mi][ni][f] = 0.f;

    {
#pragma unroll
        for (int i = 0; i < 4; ++i) {
            int idx = i * 256 + tid;
            int r = idx >> 3, c = (idx & 7) * 4;
            float4 v = *reinterpret_cast<const float4*>(&A[(size_t)(brow + r) * K + c]);
            uint4 t = { f2tf32(v.x), f2tf32(v.y), f2tf32(v.z), f2tf32(v.w) };
            *reinterpret_cast<uint4*>(&Abuf[0][r * ASTR + c]) = t;
        }
#pragma unroll
        for (int i = 0; i < 4; ++i) {
            int idx = i * 256 + tid;
            int r = idx >> 5, c = (idx & 31) * 4;
            float4 v = *reinterpret_cast<const float4*>(&W[(size_t)r * N + bcol + c]);
            uint4 t = { f2tf32(v.x), f2tf32(v.y), f2tf32(v.z), f2tf32(v.w) };
            *reinterpret_cast<uint4*>(&Bbuf[0][r * BSTR + c]) = t;
        }
    }
    __syncthreads();

    const int iters = K / 32;
    for (int kt = 0; kt < iters; ++kt) {
        const int buf = kt & 1;
        const bool has_next = (kt + 1 < iters);
        float4 aR[4], bR[4];
        if (has_next) {
            const int k0 = (kt + 1) * 32;
#pragma unroll
            for (int i = 0; i < 4; ++i) {
                int idx = i * 256 + tid;
                int r = idx >> 3, c = (idx & 7) * 4;
                aR[i] = *reinterpret_cast<const float4*>(&A[(size_t)(brow + r) * K + k0 + c]);
            }
#pragma unroll
            for (int i = 0; i < 4; ++i) {
                int idx = i * 256 + tid;
                int r = idx >> 5, c = (idx & 31) * 4;
                bR[i] = *reinterpret_cast<const float4*>(&W[(size_t)(k0 + r) * N + bcol + c]);
            }
        }

        const float* As = Abuf[buf];
        const float* Bs = Bbuf[buf];
#pragma unroll
        for (int kk = 0; kk < 4; ++kk) {
            const int kb = kk * 8;
            uint32_t af[4][4], bf[4][2];
#pragma unroll
            for (int mi = 0; mi < 4; ++mi) {
                int r0 = wm * 64 + mi * 16 + g;
                af[mi][0] = __float_as_uint(As[r0 * ASTR + kb + tig]);
                af[mi][1] = __float_as_uint(As[(r0 + 8) * ASTR + kb + tig]);
                af[mi][2] = __float_as_uint(As[r0 * ASTR + kb + tig + 4]);
                af[mi][3] = __float_as_uint(As[(r0 + 8) * ASTR + kb + tig + 4]);
            }
#pragma unroll
            for (int ni = 0; ni < 4; ++ni) {
                int c0 = wn * 32 + ni * 8 + g;
                bf[ni][0] = __float_as_uint(Bs[(kb + tig) * BSTR + c0]);
                bf[ni][1] = __float_as_uint(Bs[(kb + tig + 4) * BSTR + c0]);
            }
#pragma unroll
            for (int mi = 0; mi < 4; ++mi)
#pragma unroll
                for (int ni = 0; ni < 4; ++ni)
                    mma_tf32(acc[mi][ni], af[mi], bf[ni]);
        }

        if (has_next) {
            const int nb = buf ^ 1;
#pragma unroll
            for (int i = 0; i < 4; ++i) {
                int idx = i * 256 + tid;
                int r = idx >> 3, c = (idx & 7) * 4;
                uint4 t = { f2tf32(aR[i].x), f2tf32(aR[i].y), f2tf32(aR[i].z), f2tf32(aR[i].w) };
                *reinterpret_cast<uint4*>(&Abuf[nb][r * ASTR + c]) = t;
            }
#pragma unroll
            for (int i = 0; i < 4; ++i) {
                int idx = i * 256 + tid;
                int r = idx >> 5, c = (idx & 31) * 4;
                uint4 t = { f2tf32(bR[i].x), f2tf32(bR[i].y), f2tf32(bR[i].z), f2tf32(bR[i].w) };
                *reinterpret_cast<uint4*>(&Bbuf[nb][r * BSTR + c]) = t;
            }
        }
        __syncthreads();
    }

#pragma unroll
    for (int mi = 0; mi < 4; ++mi) {
        int r0 = brow + wm * 64 + mi * 16 + g;
#pragma unroll
        for (int ni = 0; ni < 4; ++ni) {
            int c0 = bcol + wn * 32 + ni * 8 + 2 * tig;
            float2 v0 = make_float2(acc[mi][ni][0], acc[mi][ni][1]);
            float2 v1 = make_float2(acc[mi][ni][2], acc[mi][ni][3]);
            *reinterpret_cast<float2*>(&C[(size_t)r0 * N + c0])       = v0;
            *reinterpret_cast<float2*>(&C[(size_t)(r0 + 8) * N + c0]) = v1;
        }
    }
}

// ---------------------------------------------------------------------------
// RoPE (interleaved pairs) in-place on q and k.
// ---------------------------------------------------------------------------
__global__ void rope_kernel(const float* __restrict__ fc, const int* __restrict__ pos) {
    int idx = blockIdx.x * blockDim.x + threadIdx.x;
    const int NQ = S_LEN * NHQ * (HD / 2);
    const int NK = S_LEN * NKV * (HD / 2);
    if (idx < NQ) {
        int d = idx & 63, rest = idx >> 6;
        int h = rest & (NHQ - 1), s = rest >> 4;
        int p = pos[s];
        float c = fc[p * HD + d * 2], sn = fc[p * HD + d * 2 + 1];
        float* ptr = g_q + ((size_t)s * (NHQ * HD) + h * HD + d * 2);
        float a = ptr[0], b = ptr[1];
        ptr[0] = a * c - b * sn;
        ptr[1] = a * sn + b * c;
    } else if (idx < NQ + NK) {
        int j = idx - NQ;
        int d = j & 63, rest = j >> 6;
        int h = rest & (NKV - 1), s = rest >> 2;
        int p = pos[s];
        float c = fc[p * HD + d * 2], sn = fc[p * HD + d * 2 + 1];
        float* ptr = g_k + ((size_t)s * (NKV * HD) + h * HD + d * 2);
        float a = ptr[0], b = ptr[1];
        ptr[0] = a * c - b * sn;
        ptr[1] = a * sn + b * c;
    }
}

// ---------------------------------------------------------------------------
// Flash attention on mma.sync tf32. CTA = (head, 128 q-rows), 8 warps,
// warp = 16 q-rows. 64-key tiles, online softmax in fragments.
// ---------------------------------------------------------------------------
#define QS 132
#define KSS 132
#define VSS 136
#define PSS 68
#define ATT_SMEM ((128*QS + 64*KSS + 64*VSS + 128*PSS) * 4)

__global__ __launch_bounds__(256, 1) void attn_mma(float* __restrict__ out) {
    extern __shared__ uint32_t smu[];
    uint32_t* Qs = smu;                 // [128][132] tf32
    uint32_t* Ks = Qs + 128 * QS;       // [64][132]  tf32
    uint32_t* Vs = Ks + 64 * KSS;       // [64][136]  tf32
    uint32_t* Ps = Vs + 64 * VSS;       // [128][68]  tf32

    const int h   = blockIdx.x;
    const int q0  = blockIdx.y * 128;
    const int kvh = h >> 2;
    const int tid = threadIdx.x;
    const int lane = tid & 31;
    const int wq  = tid >> 5;           // warp owns q-rows [wq*16, wq*16+16)
    const int g   = lane >> 2;
    const int tig = lane & 3;
    const int rb  = wq * 16;

    const float scale = 0.08838834764831845f;
    const float NEG = -1e30f, GUARD = -1e29f;

    // load Q tile (128x128) as tf32
#pragma unroll
    for (int i = 0; i < 16; ++i) {
        int idx = i * 256 + tid;
        int r = idx >> 5, c = (idx & 31) * 4;
        float4 v = *reinterpret_cast<const float4*>(&g_q[(size_t)(q0 + r) * (NHQ * HD) + h * HD + c]);
        uint4 t = { f2tf32(v.x), f2tf32(v.y), f2tf32(v.z), f2tf32(v.w) };
        *reinterpret_cast<uint4*>(&Qs[r * QS + c]) = t;
    }

    float m0 = NEG, m1 = NEG, l0 = 0.f, l1 = 0.f;
    float o[16][4];
#pragma unroll
    for (int nf = 0; nf < 16; ++nf)
#pragma unroll
        for (int f = 0; f < 4; ++f) o[nf][f] = 0.f;

    int lo = q0 - (WIN - 1); if (lo < 0) lo = 0;
    const int kb_lo = lo >> 6;
    const int kb_hi = (q0 + 127) >> 6;

    __syncthreads();

    for (int kb = kb_lo; kb <= kb_hi; ++kb) {
        const int t0 = kb * 64;
        // load K,V tiles (64x128) as tf32
#pragma unroll
        for (int i = 0; i < 8; ++i) {
            int idx = i * 256 + tid;
            int r = idx >> 5, c = (idx & 31) * 4;
            size_t gaddr = (size_t)(t0 + r) * (NKV * HD) + kvh * HD + c;
            float4 kv = *reinterpret_cast<const float4*>(&g_k[gaddr]);
            float4 vv = *reinterpret_cast<const float4*>(&g_v[gaddr]);
            uint4 tk = { f2tf32(kv.x), f2tf32(kv.y), f2tf32(kv.z), f2tf32(kv.w) };
            uint4 tv = { f2tf32(vv.x), f2tf32(vv.y), f2tf32(vv.z), f2tf32(vv.w) };
            *reinterpret_cast<uint4*>(&Ks[r * KSS + c]) = tk;
            *reinterpret_cast<uint4*>(&Vs[r * VSS + c]) = tv;
        }
        __syncthreads();

        // ---- S = Q @ K^T (warp: 16 x 64) ----
        float s[8][4];
#pragma unroll
        for (int nf = 0; nf < 8; ++nf)
#pragma unroll
            for (int f = 0; f < 4; ++f) s[nf][f] = 0.f;

#pragma unroll
        for (int ks = 0; ks < 16; ++ks) {
            const int k0 = ks * 8;
            uint32_t a[4];
            a[0] = Qs[(rb + g) * QS + k0 + tig];
            a[1] = Qs[(rb + g + 8) * QS + k0 + tig];
            a[2] = Qs[(rb + g) * QS + k0 + tig + 4];
            a[3] = Qs[(rb + g + 8) * QS + k0 + tig + 4];
#pragma unroll
            for (int nf = 0; nf < 8; ++nf) {
                uint32_t b[2];
                b[0] = Ks[(nf * 8 + g) * KSS + k0 + tig];
                b[1] = Ks[(nf * 8 + g) * KSS + k0 + tig + 4];
                mma_tf32(s[nf], a, b);
            }
        }

        // ---- mask + scale ----
        const int r0g = q0 + rb + g, r1g = r0g + 8;
#pragma unroll
        for (int nf = 0; nf < 8; ++nf) {
            int c0 = t0 + nf * 8 + 2 * tig;
            int c1 = c0 + 1;
            bool ok00 = (c0 <= r0g) && (r0g - c0 < WIN);
            bool ok01 = (c1 <= r0g) && (r0g - c1 < WIN);
            bool ok10 = (c0 <= r1g) && (r1g - c0 < WIN);
            bool ok11 = (c1 <= r1g) && (r1g - c1 < WIN);
            s[nf][0] = ok00 ? s[nf][0] * scale : NEG;
            s[nf][1] = ok01 ? s[nf][1] * scale : NEG;
            s[nf][2] = ok10 ? s[nf][2] * scale : NEG;
            s[nf][3] = ok11 ? s[nf][3] * scale : NEG;
        }

        // ---- online softmax (rows g and g+8) ----
        float mt0 = NEG, mt1 = NEG;
#pragma unroll
        for (int nf = 0; nf < 8; ++nf) {
            mt0 = fmaxf(mt0, fmaxf(s[nf][0], s[nf][1]));
            mt1 = fmaxf(mt1, fmaxf(s[nf][2], s[nf][3]));
        }
        mt0 = fmaxf(mt0, __shfl_xor_sync(0xffffffffu, mt0, 1));
        mt0 = fmaxf(mt0, __shfl_xor_sync(0xffffffffu, mt0, 2));
        mt1 = fmaxf(mt1, __shfl_xor_sync(0xffffffffu, mt1, 1));
        mt1 = fmaxf(mt1, __shfl_xor_sync(0xffffffffu, mt1, 2));

        float mn0 = fmaxf(m0, mt0), mn1 = fmaxf(m1, mt1);
        float esc0 = (m0 > GUARD) ? __expf(m0 - mn0) : 0.f;
        float esc1 = (m1 > GUARD) ? __expf(m1 - mn1) : 0.f;

        float rs0 = 0.f, rs1 = 0.f;
#pragma unroll
        for (int nf = 0; nf < 8; ++nf) {
            float p00 = (s[nf][0] > GUARD) ? __expf(s[nf][0] - mn0) : 0.f;
            float p01 = (s[nf][1] > GUARD) ? __expf(s[nf][1] - mn0) : 0.f;
            float p10 = (s[nf][2] > GUARD) ? __expf(s[nf][2] - mn1) : 0.f;
            float p11 = (s[nf][3] > GUARD) ? __expf(s[nf][3] - mn1) : 0.f;
            rs0 += p00 + p01;
            rs1 += p10 + p11;
            uint2 w0 = { f2tf32(p00), f2tf32(p01) };
            uint2 w1 = { f2tf32(p10), f2tf32(p11) };
            *reinterpret_cast<uint2*>(&Ps[(rb + g) * PSS + nf * 8 + 2 * tig])     = w0;
            *reinterpret_cast<uint2*>(&Ps[(rb + g + 8) * PSS + nf * 8 + 2 * tig]) = w1;
        }
        rs0 += __shfl_xor_sync(0xffffffffu, rs0, 1);
        rs0 += __shfl_xor_sync(0xffffffffu, rs0, 2);
        rs1 += __shfl_xor_sync(0xffffffffu, rs1, 1);
        rs1 += __shfl_xor_sync(0xffffffffu, rs1, 2);

        l0 = l0 * esc0 + rs0; m0 = mn0;
        l1 = l1 * esc1 + rs1; m1 = mn1;

#pragma unroll
        for (int nf = 0; nf < 16; ++nf) {
            o[nf][0] *= esc0; o[nf][1] *= esc0;
            o[nf][2] *= esc1; o[nf][3] *= esc1;
        }
        __syncwarp(0xffffffffu);   // Ps rows are warp-private: warp-level ordering suffices

        // ---- O += P @ V (warp: 16 x 128) ----
#pragma unroll
        for (int ks = 0; ks < 8; ++ks) {
            const int k0 = ks * 8;
            uint32_t a[4];
            a[0] = Ps[(rb + g) * PSS + k0 + tig];
            a[1] = Ps[(rb + g + 8) * PSS + k0 + tig];
            a[2] = Ps[(rb + g) * PSS + k0 + tig + 4];
            a[3] = Ps[(rb + g + 8) * PSS + k0 + tig + 4];
#pragma unroll
            for (int nf = 0; nf < 16; ++nf) {
                uint32_t b[2];
                b[0] = Vs[(k0 + tig) * VSS + nf * 8 + g];
                b[1] = Vs[(k0 + tig + 4) * VSS + nf * 8 + g];
                mma_tf32(o[nf], a, b);
            }
        }
        __syncthreads();   // protect Ks/Vs before next tile load
    }

    // ---- epilogue ----
    const float inv0 = 1.f / l0, inv1 = 1.f / l1;
    const int qr0 = q0 + rb + g, qr1 = qr0 + 8;
#pragma unroll
    for (int nf = 0; nf < 16; ++nf) {
        int c0 = h * HD + nf * 8 + 2 * tig;
        float2 v0 = make_float2(o[nf][0] * inv0, o[nf][1] * inv0);
        float2 v1 = make_float2(o[nf][2] * inv1, o[nf][3] * inv1);
        *reinterpret_cast<float2*>(&out[(size_t)qr0 * (NHQ * HD) + c0]) = v0;
        *reinterpret_cast<float2*>(&out[(size_t)qr1 * (NHQ * HD) + c0]) = v1;
    }
}

// ---------------------------------------------------------------------------
extern "C" void kernel_launch(void* const* d_in, const int* in_sizes, int n_in,
                              void* d_out, int out_size) {
    const float* hs  = (const float*)d_in[0];
    const float* fc  = (const float*)d_in[1];
    const int*   pos = (const int*)d_in[4];
    const float* Wq  = (const float*)d_in[5];
    const float* Wk  = (const float*)d_in[6];
    const float* Wv  = (const float*)d_in[7];
    const float* Wo  = (const float*)d_in[8];
    float* out = (float*)d_out;

    float *qp, *kp, *vp, *ap;
    cudaGetSymbolAddress((void**)&qp, g_q);
    cudaGetSymbolAddress((void**)&kp, g_k);
    cudaGetSymbolAddress((void**)&vp, g_v);
    cudaGetSymbolAddress((void**)&ap, g_attn);

    cudaFuncSetAttribute(gemm_mma, cudaFuncAttributeMaxDynamicSharedMemorySize, GEMM_SMEM);
    cudaFuncSetAttribute(attn_mma, cudaFuncAttributeMaxDynamicSharedMemorySize, ATT_SMEM);

    // QKV projections
    gemm_mma<<<dim3((NHQ * HD) / 128, S_LEN / 128), 256, GEMM_SMEM>>>(hs, Wq, qp, S_LEN, NHQ * HD, HID);
    gemm_mma<<<dim3((NKV * HD) / 128, S_LEN / 128), 256, GEMM_SMEM>>>(hs, Wk, kp, S_LEN, NKV * HD, HID);
    gemm_mma<<<dim3((NKV * HD) / 128, S_LEN / 128), 256, GEMM_SMEM>>>(hs, Wv, vp, S_LEN, NKV * HD, HID);

    // RoPE
    {
        int total = S_LEN * NHQ * (HD / 2) + S_LEN * NKV * (HD / 2);
        rope_kernel<<<(total + 255) / 256, 256>>>(fc, pos);
    }

    // Attention (tensor-core flash)
    attn_mma<<<dim3(NHQ, S_LEN / 128), 256, ATT_SMEM>>>(ap);

    // Output projection
    gemm_mma<<<dim3(HID / 128, S_LEN / 128), 256, GEMM_SMEM>>>(ap, Wo, out, S_LEN, HID, HID);
}

// round 6
// speedup vs baseline: 3.8038x; 1.8246x over previous
#include <cuda_runtime.h>
#include <cstdint>
#include <math.h>

#define S_LEN 2048
#define HID   2048
#define NHQ   16
#define NKV   4
#define HD    128
#define WIN   1024

// ---------------- scratch (no cudaMalloc allowed) ----------------
__device__ float g_q[S_LEN * NHQ * HD];
__device__ float g_k[S_LEN * NKV * HD];
__device__ float g_v[S_LEN * NKV * HD];
__device__ float g_attn[S_LEN * NHQ * HD];
__device__ float g_hsr[S_LEN * HID];          // rounded hidden_state
__device__ float g_wqr[HID * (NHQ * HD)];     // rounded weights
__device__ float g_wkr[HID * (NKV * HD)];
__device__ float g_wvr[HID * (NKV * HD)];
__device__ float g_wor[(NHQ * HD) * HID];

__device__ __forceinline__ uint32_t f2tf32(float x) {
    uint32_t r; asm("cvt.rna.tf32.f32 %0, %1;" : "=r"(r) : "f"(x)); return r;
}
__device__ __forceinline__ float tf32r(float x) { return __uint_as_float(f2tf32(x)); }

__device__ __forceinline__ void mma_tf32(float c[4], const uint32_t a[4], const uint32_t b[2]) {
    asm volatile("mma.sync.aligned.m16n8k8.row.col.f32.tf32.tf32.f32 "
        "{%0,%1,%2,%3}, {%4,%5,%6,%7}, {%8,%9}, {%0,%1,%2,%3};"
        : "+f"(c[0]), "+f"(c[1]), "+f"(c[2]), "+f"(c[3])
        : "r"(a[0]), "r"(a[1]), "r"(a[2]), "r"(a[3]), "r"(b[0]), "r"(b[1]));
}
__device__ __forceinline__ uint32_t smem_u32(const void* p) {
    uint32_t a;
    asm("{ .reg .u64 t; cvta.to.shared.u64 t, %1; cvt.u32.u64 %0, t; }" : "=r"(a) : "l"(p));
    return a;
}
__device__ __forceinline__ void cp16(uint32_t s, const void* g) {
    asm volatile("cp.async.ca.shared.global [%0], [%1], 16;" :: "r"(s), "l"(g));
}
#define CP_COMMIT() asm volatile("cp.async.commit_group;" ::: "memory")
#define CP_WAIT1()  asm volatile("cp.async.wait_group 1;" ::: "memory")

// ---------------------------------------------------------------------------
// elementwise tf32 rounding pass
// ---------------------------------------------------------------------------
__global__ void round_tf32(const float* __restrict__ src, float* __restrict__ dst, int n) {
    int i = (blockIdx.x * blockDim.x + threadIdx.x) * 4;
    if (i < n) {
        float4 v = *reinterpret_cast<const float4*>(src + i);
        v.x = tf32r(v.x); v.y = tf32r(v.y); v.z = tf32r(v.z); v.w = tf32r(v.w);
        *reinterpret_cast<float4*>(dst + i) = v;
    }
}

// ---------------------------------------------------------------------------
// cp.async 3-stage tf32 GEMM. C = A[M,K] @ W[K,N] (pre-rounded operands).
// CTA tile (MI*32) x 256, 8 warps (2 x 4), warp tile (MI*16) x 64.
// Fused variant: if bcol >= nsplit, use W2/C2 with local column bcol-nsplit
// (N is then the width of EACH half).
// ---------------------------------------------------------------------------
#define ASTRIDE 36
#define BSTRIDE 264

template<int MI>
__global__ __launch_bounds__(256, 1) void gemm_cp(const float* __restrict__ A,
                                                  const float* __restrict__ W,
                                                  const float* __restrict__ W2,
                                                  float* __restrict__ C,
                                                  float* __restrict__ C2,
                                                  int N, int K, int nsplit) {
    constexpr int A_FLOATS = MI * 32 * ASTRIDE;
    constexpr int B_FLOATS = 32 * BSTRIDE;
    constexpr int STAGE = A_FLOATS + B_FLOATS;

    extern __shared__ float smcp[];
    const uint32_t sbase = smem_u32(smcp);

    const int tid  = threadIdx.x;
    const int lane = tid & 31;
    const int wid  = tid >> 5;
    const int wm   = wid & 1;
    const int wn   = wid >> 1;
    const int g    = lane >> 2;
    const int tig  = lane & 3;
    const int brow = blockIdx.y * (MI * 32);
    int bcol = blockIdx.x * 256;

    if (bcol >= nsplit) { W = W2; C = C2; bcol -= nsplit; }

    float acc[MI][8][4];
#pragma unroll
    for (int mi = 0; mi < MI; ++mi)
#pragma unroll
        for (int ni = 0; ni < 8; ++ni)
#pragma unroll
            for (int f = 0; f < 4; ++f) acc[mi][ni][f] = 0.f;

    const int iters = K / 32;

    // stage issue helper (inlined twice)
#define ISSUE_STAGE(st, k0)                                                        \
    do {                                                                           \
        uint32_t soff = sbase + (uint32_t)((st) * STAGE) * 4u;                     \
        _Pragma("unroll")                                                          \
        for (int i = 0; i < MI; ++i) {                                             \
            int idx = tid + i * 256;                                               \
            int r = idx >> 3, c4 = (idx & 7) * 4;                                  \
            cp16(soff + (uint32_t)(r * ASTRIDE + c4) * 4u,                         \
                 &A[(size_t)(brow + r) * K + (k0) + c4]);                          \
        }                                                                          \
        _Pragma("unroll")                                                          \
        for (int i = 0; i < 8; ++i) {                                              \
            int idx = tid + i * 256;                                               \
            int r = idx >> 6, c4 = (idx & 63) * 4;                                 \
            cp16(soff + (uint32_t)(A_FLOATS + r * BSTRIDE + c4) * 4u,              \
                 &W[(size_t)((k0) + r) * N + bcol + c4]);                          \
        }                                                                          \
        CP_COMMIT();                                                               \
    } while (0)

    ISSUE_STAGE(0, 0);
    ISSUE_STAGE(1, 32);

    for (int kt = 0; kt < iters; ++kt) {
        CP_WAIT1();
        __syncthreads();

        if (kt + 2 < iters) {
            ISSUE_STAGE((kt + 2) % 3, (kt + 2) * 32);
        } else {
            CP_COMMIT();   // keep group counting uniform
        }

        const float* As = smcp + (kt % 3) * STAGE;
        const float* Bs = As + A_FLOATS;

#pragma unroll
        for (int kk = 0; kk < 4; ++kk) {
            const int kb = kk * 8;
            uint32_t af[MI][4], bf[8][2];
#pragma unroll
            for (int mi = 0; mi < MI; ++mi) {
                int r0 = wm * (MI * 16) + mi * 16 + g;
                af[mi][0] = __float_as_uint(As[r0 * ASTRIDE + kb + tig]);
                af[mi][1] = __float_as_uint(As[(r0 + 8) * ASTRIDE + kb + tig]);
                af[mi][2] = __float_as_uint(As[r0 * ASTRIDE + kb + tig + 4]);
                af[mi][3] = __float_as_uint(As[(r0 + 8) * ASTRIDE + kb + tig + 4]);
            }
#pragma unroll
            for (int ni = 0; ni < 8; ++ni) {
                int c0 = wn * 64 + ni * 8 + g;
                bf[ni][0] = __float_as_uint(Bs[(kb + tig) * BSTRIDE + c0]);
                bf[ni][1] = __float_as_uint(Bs[(kb + tig + 4) * BSTRIDE + c0]);
            }
#pragma unroll
            for (int mi = 0; mi < MI; ++mi)
#pragma unroll
                for (int ni = 0; ni < 8; ++ni)
                    mma_tf32(acc[mi][ni], af[mi], bf[ni]);
        }
        __syncthreads();
    }
#undef ISSUE_STAGE

    // epilogue
#pragma unroll
    for (int mi = 0; mi < MI; ++mi) {
        int r0 = brow + wm * (MI * 16) + mi * 16 + g;
#pragma unroll
        for (int ni = 0; ni < 8; ++ni) {
            int c0 = bcol + wn * 64 + ni * 8 + 2 * tig;
            float2 v0 = make_float2(acc[mi][ni][0], acc[mi][ni][1]);
            float2 v1 = make_float2(acc[mi][ni][2], acc[mi][ni][3]);
            *reinterpret_cast<float2*>(&C[(size_t)r0 * N + c0])       = v0;
            *reinterpret_cast<float2*>(&C[(size_t)(r0 + 8) * N + c0]) = v1;
        }
    }
}

// ---------------------------------------------------------------------------
// RoPE (interleaved pairs) in-place, outputs tf32-rounded.
// ---------------------------------------------------------------------------
__global__ void rope_kernel(const float* __restrict__ fc, const int* __restrict__ pos) {
    int idx = blockIdx.x * blockDim.x + threadIdx.x;
    const int NQ = S_LEN * NHQ * (HD / 2);
    const int NK = S_LEN * NKV * (HD / 2);
    if (idx < NQ) {
        int d = idx & 63, rest = idx >> 6;
        int h = rest & (NHQ - 1), s = rest >> 4;
        int p = pos[s];
        float c = fc[p * HD + d * 2], sn = fc[p * HD + d * 2 + 1];
        float* ptr = g_q + ((size_t)s * (NHQ * HD) + h * HD + d * 2);
        float a = ptr[0], b = ptr[1];
        ptr[0] = tf32r(a * c - b * sn);
        ptr[1] = tf32r(a * sn + b * c);
    } else if (idx < NQ + NK) {
        int j = idx - NQ;
        int d = j & 63, rest = j >> 6;
        int h = rest & (NKV - 1), s = rest >> 2;
        int p = pos[s];
        float c = fc[p * HD + d * 2], sn = fc[p * HD + d * 2 + 1];
        float* ptr = g_k + ((size_t)s * (NKV * HD) + h * HD + d * 2);
        float a = ptr[0], b = ptr[1];
        ptr[0] = tf32r(a * c - b * sn);
        ptr[1] = tf32r(a * sn + b * c);
    }
}

// ---------------------------------------------------------------------------
// Flash attention on mma.sync tf32 (R5 passing version; epilogue rounds output).
// ---------------------------------------------------------------------------
#define QS 132
#define KSS 132
#define VSS 136
#define PSS 68
#define ATT_SMEM ((128*QS + 64*KSS + 64*VSS + 128*PSS) * 4)

__global__ __launch_bounds__(256, 1) void attn_mma(float* __restrict__ out) {
    extern __shared__ uint32_t smu[];
    uint32_t* Qs = smu;
    uint32_t* Ks = Qs + 128 * QS;
    uint32_t* Vs = Ks + 64 * KSS;
    uint32_t* Ps = Vs + 64 * VSS;

    const int h   = blockIdx.x;
    const int q0  = blockIdx.y * 128;
    const int kvh = h >> 2;
    const int tid = threadIdx.x;
    const int lane = tid & 31;
    const int wq  = tid >> 5;
    const int g   = lane >> 2;
    const int tig = lane & 3;
    const int rb  = wq * 16;

    const float scale = 0.08838834764831845f;
    const float NEG = -1e30f, GUARD = -1e29f;

#pragma unroll
    for (int i = 0; i < 16; ++i) {
        int idx = i * 256 + tid;
        int r = idx >> 5, c = (idx & 31) * 4;
        float4 v = *reinterpret_cast<const float4*>(&g_q[(size_t)(q0 + r) * (NHQ * HD) + h * HD + c]);
        uint4 t = { f2tf32(v.x), f2tf32(v.y), f2tf32(v.z), f2tf32(v.w) };
        *reinterpret_cast<uint4*>(&Qs[r * QS + c]) = t;
    }

    float m0 = NEG, m1 = NEG, l0 = 0.f, l1 = 0.f;
    float o[16][4];
#pragma unroll
    for (int nf = 0; nf < 16; ++nf)
#pragma unroll
        for (int f = 0; f < 4; ++f) o[nf][f] = 0.f;

    int lo = q0 - (WIN - 1); if (lo < 0) lo = 0;
    const int kb_lo = lo >> 6;
    const int kb_hi = (q0 + 127) >> 6;

    __syncthreads();

    for (int kb = kb_lo; kb <= kb_hi; ++kb) {
        const int t0 = kb * 64;
#pragma unroll
        for (int i = 0; i < 8; ++i) {
            int idx = i * 256 + tid;
            int r = idx >> 5, c = (idx & 31) * 4;
            size_t gaddr = (size_t)(t0 + r) * (NKV * HD) + kvh * HD + c;
            float4 kv = *reinterpret_cast<const float4*>(&g_k[gaddr]);
            float4 vv = *reinterpret_cast<const float4*>(&g_v[gaddr]);
            uint4 tk = { f2tf32(kv.x), f2tf32(kv.y), f2tf32(kv.z), f2tf32(kv.w) };
            uint4 tv = { f2tf32(vv.x), f2tf32(vv.y), f2tf32(vv.z), f2tf32(vv.w) };
            *reinterpret_cast<uint4*>(&Ks[r * KSS + c]) = tk;
            *reinterpret_cast<uint4*>(&Vs[r * VSS + c]) = tv;
        }
        __syncthreads();

        float s[8][4];
#pragma unroll
        for (int nf = 0; nf < 8; ++nf)
#pragma unroll
            for (int f = 0; f < 4; ++f) s[nf][f] = 0.f;

#pragma unroll
        for (int ks = 0; ks < 16; ++ks) {
            const int k0 = ks * 8;
            uint32_t a[4];
            a[0] = Qs[(rb + g) * QS + k0 + tig];
            a[1] = Qs[(rb + g + 8) * QS + k0 + tig];
            a[2] = Qs[(rb + g) * QS + k0 + tig + 4];
            a[3] = Qs[(rb + g + 8) * QS + k0 + tig + 4];
#pragma unroll
            for (int nf = 0; nf < 8; ++nf) {
                uint32_t b[2];
                b[0] = Ks[(nf * 8 + g) * KSS + k0 + tig];
                b[1] = Ks[(nf * 8 + g) * KSS + k0 + tig + 4];
                mma_tf32(s[nf], a, b);
            }
        }

        const int r0g = q0 + rb + g, r1g = r0g + 8;
#pragma unroll
        for (int nf = 0; nf < 8; ++nf) {
            int c0 = t0 + nf * 8 + 2 * tig;
            int c1 = c0 + 1;
            bool ok00 = (c0 <= r0g) && (r0g - c0 < WIN);
            bool ok01 = (c1 <= r0g) && (r0g - c1 < WIN);
            bool ok10 = (c0 <= r1g) && (r1g - c0 < WIN);
            bool ok11 = (c1 <= r1g) && (r1g - c1 < WIN);
            s[nf][0] = ok00 ? s[nf][0] * scale : NEG;
            s[nf][1] = ok01 ? s[nf][1] * scale : NEG;
            s[nf][2] = ok10 ? s[nf][2] * scale : NEG;
            s[nf][3] = ok11 ? s[nf][3] * scale : NEG;
        }

        float mt0 = NEG, mt1 = NEG;
#pragma unroll
        for (int nf = 0; nf < 8; ++nf) {
            mt0 = fmaxf(mt0, fmaxf(s[nf][0], s[nf][1]));
            mt1 = fmaxf(mt1, fmaxf(s[nf][2], s[nf][3]));
        }
        mt0 = fmaxf(mt0, __shfl_xor_sync(0xffffffffu, mt0, 1));
        mt0 = fmaxf(mt0, __shfl_xor_sync(0xffffffffu, mt0, 2));
        mt1 = fmaxf(mt1, __shfl_xor_sync(0xffffffffu, mt1, 1));
        mt1 = fmaxf(mt1, __shfl_xor_sync(0xffffffffu, mt1, 2));

        float mn0 = fmaxf(m0, mt0), mn1 = fmaxf(m1, mt1);
        float esc0 = (m0 > GUARD) ? __expf(m0 - mn0) : 0.f;
        float esc1 = (m1 > GUARD) ? __expf(m1 - mn1) : 0.f;

        float rs0 = 0.f, rs1 = 0.f;
#pragma unroll
        for (int nf = 0; nf < 8; ++nf) {
            float p00 = (s[nf][0] > GUARD) ? __expf(s[nf][0] - mn0) : 0.f;
            float p01 = (s[nf][1] > GUARD) ? __expf(s[nf][1] - mn0) : 0.f;
            float p10 = (s[nf][2] > GUARD) ? __expf(s[nf][2] - mn1) : 0.f;
            float p11 = (s[nf][3] > GUARD) ? __expf(s[nf][3] - mn1) : 0.f;
            rs0 += p00 + p01;
            rs1 += p10 + p11;
            uint2 w0 = { f2tf32(p00), f2tf32(p01) };
            uint2 w1 = { f2tf32(p10), f2tf32(p11) };
            *reinterpret_cast<uint2*>(&Ps[(rb + g) * PSS + nf * 8 + 2 * tig])     = w0;
            *reinterpret_cast<uint2*>(&Ps[(rb + g + 8) * PSS + nf * 8 + 2 * tig]) = w1;
        }
        rs0 += __shfl_xor_sync(0xffffffffu, rs0, 1);
        rs0 += __shfl_xor_sync(0xffffffffu, rs0, 2);
        rs1 += __shfl_xor_sync(0xffffffffu, rs1, 1);
        rs1 += __shfl_xor_sync(0xffffffffu, rs1, 2);

        l0 = l0 * esc0 + rs0; m0 = mn0;
        l1 = l1 * esc1 + rs1; m1 = mn1;

#pragma unroll
        for (int nf = 0; nf < 16; ++nf) {
            o[nf][0] *= esc0; o[nf][1] *= esc0;
            o[nf][2] *= esc1; o[nf][3] *= esc1;
        }
        __syncwarp(0xffffffffu);

#pragma unroll
        for (int ks = 0; ks < 8; ++ks) {
            const int k0 = ks * 8;
            uint32_t a[4];
            a[0] = Ps[(rb + g) * PSS + k0 + tig];
            a[1] = Ps[(rb + g + 8) * PSS + k0 + tig];
            a[2] = Ps[(rb + g) * PSS + k0 + tig + 4];
            a[3] = Ps[(rb + g + 8) * PSS + k0 + tig + 4];
#pragma unroll
            for (int nf = 0; nf < 16; ++nf) {
                uint32_t b[2];
                b[0] = Vs[(k0 + tig) * VSS + nf * 8 + g];
                b[1] = Vs[(k0 + tig + 4) * VSS + nf * 8 + g];
                mma_tf32(o[nf], a, b);
            }
        }
        __syncthreads();
    }

    const float inv0 = 1.f / l0, inv1 = 1.f / l1;
    const int qr0 = q0 + rb + g, qr1 = qr0 + 8;
#pragma unroll
    for (int nf = 0; nf < 16; ++nf) {
        int c0 = h * HD + nf * 8 + 2 * tig;
        float2 v0 = make_float2(tf32r(o[nf][0] * inv0), tf32r(o[nf][1] * inv0));
        float2 v1 = make_float2(tf32r(o[nf][2] * inv1), tf32r(o[nf][3] * inv1));
        *reinterpret_cast<float2*>(&out[(size_t)qr0 * (NHQ * HD) + c0]) = v0;
        *reinterpret_cast<float2*>(&out[(size_t)qr1 * (NHQ * HD) + c0]) = v1;
    }
}

// ---------------------------------------------------------------------------
extern "C" void kernel_launch(void* const* d_in, const int* in_sizes, int n_in,
                              void* d_out, int out_size) {
    const float* hs  = (const float*)d_in[0];
    const float* fc  = (const float*)d_in[1];
    const int*   pos = (const int*)d_in[4];
    const float* Wq  = (const float*)d_in[5];
    const float* Wk  = (const float*)d_in[6];
    const float* Wv  = (const float*)d_in[7];
    const float* Wo  = (const float*)d_in[8];
    float* out = (float*)d_out;

    float *qp, *kp, *vp, *ap, *hsr, *wqr, *wkr, *wvr, *wor;
    cudaGetSymbolAddress((void**)&qp,  g_q);
    cudaGetSymbolAddress((void**)&kp,  g_k);
    cudaGetSymbolAddress((void**)&vp,  g_v);
    cudaGetSymbolAddress((void**)&ap,  g_attn);
    cudaGetSymbolAddress((void**)&hsr, g_hsr);
    cudaGetSymbolAddress((void**)&wqr, g_wqr);
    cudaGetSymbolAddress((void**)&wkr, g_wkr);
    cudaGetSymbolAddress((void**)&wvr, g_wvr);
    cudaGetSymbolAddress((void**)&wor, g_wor);

    // tf32 pre-rounding passes
    {
        int n1 = S_LEN * HID;
        int n2 = HID * NKV * HD;
        round_tf32<<<n1 / 1024, 256>>>(hs, hsr, n1);
        round_tf32<<<n1 / 1024, 256>>>(Wq, wqr, n1);
        round_tf32<<<n2 / 1024, 256>>>(Wk, wkr, n2);
        round_tf32<<<n2 / 1024, 256>>>(Wv, wvr, n2);
        round_tf32<<<n1 / 1024, 256>>>(Wo, wor, n1);
    }

    constexpr int SM4 = 3 * (4 * 32 * ASTRIDE + 32 * BSTRIDE) * 4;
    constexpr int SM2 = 3 * (2 * 32 * ASTRIDE + 32 * BSTRIDE) * 4;
    cudaFuncSetAttribute(gemm_cp<4>, cudaFuncAttributeMaxDynamicSharedMemorySize, SM4);
    cudaFuncSetAttribute(gemm_cp<2>, cudaFuncAttributeMaxDynamicSharedMemorySize, SM2);
    cudaFuncSetAttribute(attn_mma,   cudaFuncAttributeMaxDynamicSharedMemorySize, ATT_SMEM);

    // Q projection: 128x256 tiles, grid 8x16 = 128 CTAs (single wave)
    gemm_cp<4><<<dim3(8, 16), 256, SM4>>>(hsr, wqr, wqr, qp, qp, NHQ * HD, HID, 1 << 30);

    // fused K+V projection: 64x256 tiles, grid 4x32 = 128 CTAs
    gemm_cp<2><<<dim3(4, 32), 256, SM2>>>(hsr, wkr, wvr, kp, vp, NKV * HD, HID, NKV * HD);

    // RoPE (rounds outputs)
    {
        int total = S_LEN * NHQ * (HD / 2) + S_LEN * NKV * (HD / 2);
        rope_kernel<<<(total + 255) / 256, 256>>>(fc, pos);
    }

    // Attention (tensor-core flash, rounds output)
    attn_mma<<<dim3(NHQ, S_LEN / 128), 256, ATT_SMEM>>>(ap);

    // O projection
    gemm_cp<4><<<dim3(8, 16), 256, SM4>>>(ap, wor, wor, out, out, HID, NHQ * HD, 1 << 30);
}

// round 7
// speedup vs baseline: 5.6873x; 1.4952x over previous
#include <cuda_runtime.h>
#include <cuda_fp16.h>
#include <cstdint>
#include <math.h>

#define S_LEN 2048
#define HID   2048
#define NHQ   16
#define NKV   4
#define HD    128
#define WIN   1024

// ---------------- scratch (no cudaMalloc allowed) ----------------
__device__ float    g_q[S_LEN * NHQ * HD];
__device__ float    g_k[S_LEN * NKV * HD];
__device__ float    g_v[S_LEN * NKV * HD];
__device__ __half   g_hsh[S_LEN * HID];                // fp16 hidden state (A operand)
__device__ uint32_t g_attnh[S_LEN * (NHQ * HD) / 2];   // fp16 attention out (half2 view)
__device__ uint32_t g_wqp[(HID / 2) * (NHQ * HD)];     // k-pair-packed fp16 weights
__device__ uint32_t g_wkp[(HID / 2) * (NKV * HD)];
__device__ uint32_t g_wvp[(HID / 2) * (NKV * HD)];
__device__ uint32_t g_wop[((NHQ * HD) / 2) * HID];

__device__ __forceinline__ uint32_t pack2(float a, float b) {
    __half2 h = __floats2half2_rn(a, b);
    return *reinterpret_cast<uint32_t*>(&h);
}
__device__ __forceinline__ void mma_h16(float c[4], const uint32_t a[4], const uint32_t b[2]) {
    asm volatile("mma.sync.aligned.m16n8k16.row.col.f32.f16.f16.f32 "
        "{%0,%1,%2,%3}, {%4,%5,%6,%7}, {%8,%9}, {%0,%1,%2,%3};"
        : "+f"(c[0]), "+f"(c[1]), "+f"(c[2]), "+f"(c[3])
        : "r"(a[0]), "r"(a[1]), "r"(a[2]), "r"(a[3]), "r"(b[0]), "r"(b[1]));
}
__device__ __forceinline__ uint32_t smem_u32(const void* p) {
    uint32_t a;
    asm("{ .reg .u64 t; cvta.to.shared.u64 t, %1; cvt.u32.u64 %0, t; }" : "=r"(a) : "l"(p));
    return a;
}
__device__ __forceinline__ void cp16(uint32_t s, const void* g) {
    asm volatile("cp.async.ca.shared.global [%0], [%1], 16;" :: "r"(s), "l"(g));
}
#define CP_COMMIT() asm volatile("cp.async.commit_group;" ::: "memory")
#define CP_WAIT1()  asm volatile("cp.async.wait_group 1;" ::: "memory")

// ---------------------------------------------------------------------------
// fp32 -> fp16 convert (row-major A operand); 8 elems/thread
// ---------------------------------------------------------------------------
__global__ void conv_half(const float* __restrict__ src, __half* __restrict__ dst) {
    int i = (blockIdx.x * blockDim.x + threadIdx.x) * 8;
    float4 v0 = *reinterpret_cast<const float4*>(src + i);
    float4 v1 = *reinterpret_cast<const float4*>(src + i + 4);
    uint4 o = { pack2(v0.x, v0.y), pack2(v0.z, v0.w), pack2(v1.x, v1.y), pack2(v1.z, v1.w) };
    *reinterpret_cast<uint4*>(dst + i) = o;
}

// ---------------------------------------------------------------------------
// weight pack: W[K][N] fp32 -> Wp[K/2][N] half2( W[2r][n], W[2r+1][n] )
// ---------------------------------------------------------------------------
__global__ void pack_w(const float* __restrict__ W, uint32_t* __restrict__ Wp, int N) {
    int i = blockIdx.x * blockDim.x + threadIdx.x;
    int nc4 = N >> 2;
    int r2 = i / nc4, c = (i % nc4) * 4;
    float4 a = *reinterpret_cast<const float4*>(&W[(size_t)(2 * r2) * N + c]);
    float4 b = *reinterpret_cast<const float4*>(&W[(size_t)(2 * r2 + 1) * N + c]);
    uint4 o = { pack2(a.x, b.x), pack2(a.y, b.y), pack2(a.z, b.z), pack2(a.w, b.w) };
    *reinterpret_cast<uint4*>(&Wp[(size_t)r2 * N + c]) = o;
}

// ---------------------------------------------------------------------------
// fp16 cp.async GEMM: C = A[M,K] @ W[K,N]. CTA 128x256, 8 warps (2x4),
// warp 64x64, K-tile 32, 3 stages. 3-way column split for fused QKV.
// ---------------------------------------------------------------------------
#define AS2 20     // u32 stride of A smem row (16 half2 + 4 pad)
#define BS2 264    // u32 stride of B smem row (256 half2 + 8 pad)
#define A_U32 (128 * AS2)
#define B_U32 (16 * BS2)
#define STG_U32 (A_U32 + B_U32)
#define GEMM_SMEM (3 * STG_U32 * 4)

__global__ __launch_bounds__(256, 1) void gemm_h(const __half* __restrict__ Ah, int K,
                                                 const uint32_t* __restrict__ Wp0, float* __restrict__ C0, int N0, int nb0,
                                                 const uint32_t* __restrict__ Wp1, float* __restrict__ C1, int N1, int nb1,
                                                 const uint32_t* __restrict__ Wp2, float* __restrict__ C2, int N2) {
    extern __shared__ uint32_t smg[];
    const uint32_t sbase = smem_u32(smg);

    const int tid  = threadIdx.x;
    const int lane = tid & 31;
    const int wid  = tid >> 5;
    const int wm   = wid & 1;
    const int wn   = wid >> 1;
    const int g    = lane >> 2;
    const int tig  = lane & 3;
    const int brow = blockIdx.y * 128;

    const uint32_t* Wp; float* C; int N, cloc;
    {
        int bx = blockIdx.x;
        if (bx < nb0)            { Wp = Wp0; C = C0; N = N0; cloc = bx * 256; }
        else if (bx < nb0 + nb1) { Wp = Wp1; C = C1; N = N1; cloc = (bx - nb0) * 256; }
        else                     { Wp = Wp2; C = C2; N = N2; cloc = (bx - nb0 - nb1) * 256; }
    }

    float acc[4][8][4];
#pragma unroll
    for (int mi = 0; mi < 4; ++mi)
#pragma unroll
        for (int ni = 0; ni < 8; ++ni)
#pragma unroll
            for (int f = 0; f < 4; ++f) acc[mi][ni][f] = 0.f;

    const int iters = K / 32;

#define ISSUE_STAGE(st, k0)                                                         \
    do {                                                                            \
        uint32_t soff = sbase + (uint32_t)((st) * STG_U32) * 4u;                    \
        _Pragma("unroll")                                                           \
        for (int i = 0; i < 2; ++i) {                                               \
            int idx = tid + i * 256;                                                \
            int r = idx >> 2, ch = idx & 3;                                         \
            cp16(soff + (uint32_t)(r * AS2 * 4 + ch * 16),                          \
                 &Ah[(size_t)(brow + r) * K + (k0) + ch * 8]);                      \
        }                                                                           \
        _Pragma("unroll")                                                           \
        for (int i = 0; i < 4; ++i) {                                               \
            int idx = tid + i * 256;                                                \
            int r = idx >> 6, ch = idx & 63;                                        \
            cp16(soff + (uint32_t)(A_U32 * 4 + r * BS2 * 4 + ch * 16),              \
                 &Wp[(size_t)((k0) / 2 + r) * N + cloc + ch * 4]);                  \
        }                                                                           \
        CP_COMMIT();                                                                \
    } while (0)

    ISSUE_STAGE(0, 0);
    ISSUE_STAGE(1, 32);

    for (int kt = 0; kt < iters; ++kt) {
        CP_WAIT1();
        __syncthreads();

        if (kt + 2 < iters) {
            ISSUE_STAGE((kt + 2) % 3, (kt + 2) * 32);
        } else {
            CP_COMMIT();
        }

        const uint32_t* As = smg + (kt % 3) * STG_U32;
        const uint32_t* Bs = As + A_U32;

#pragma unroll
        for (int kk = 0; kk < 2; ++kk) {
            const int kb2 = kk * 8;
            uint32_t af[4][4], bf[8][2];
#pragma unroll
            for (int mi = 0; mi < 4; ++mi) {
                int r0 = wm * 64 + mi * 16 + g;
                af[mi][0] = As[r0 * AS2 + kb2 + tig];
                af[mi][1] = As[(r0 + 8) * AS2 + kb2 + tig];
                af[mi][2] = As[r0 * AS2 + kb2 + tig + 4];
                af[mi][3] = As[(r0 + 8) * AS2 + kb2 + tig + 4];
            }
#pragma unroll
            for (int ni = 0; ni < 8; ++ni) {
                int c0 = wn * 64 + ni * 8 + g;
                bf[ni][0] = Bs[(kb2 + tig) * BS2 + c0];
                bf[ni][1] = Bs[(kb2 + tig + 4) * BS2 + c0];
            }
#pragma unroll
            for (int mi = 0; mi < 4; ++mi)
#pragma unroll
                for (int ni = 0; ni < 8; ++ni)
                    mma_h16(acc[mi][ni], af[mi], bf[ni]);
        }
        __syncthreads();
    }
#undef ISSUE_STAGE

#pragma unroll
    for (int mi = 0; mi < 4; ++mi) {
        int r0 = brow + wm * 64 + mi * 16 + g;
#pragma unroll
        for (int ni = 0; ni < 8; ++ni) {
            int c0 = cloc + wn * 64 + ni * 8 + 2 * tig;
            float2 v0 = make_float2(acc[mi][ni][0], acc[mi][ni][1]);
            float2 v1 = make_float2(acc[mi][ni][2], acc[mi][ni][3]);
            *reinterpret_cast<float2*>(&C[(size_t)r0 * N + c0])       = v0;
            *reinterpret_cast<float2*>(&C[(size_t)(r0 + 8) * N + c0]) = v1;
        }
    }
}

// ---------------------------------------------------------------------------
// RoPE (interleaved pairs) in-place on q and k (fp32).
// ---------------------------------------------------------------------------
__global__ void rope_kernel(const float* __restrict__ fc, const int* __restrict__ pos) {
    int idx = blockIdx.x * blockDim.x + threadIdx.x;
    const int NQ = S_LEN * NHQ * (HD / 2);
    const int NK = S_LEN * NKV * (HD / 2);
    if (idx < NQ) {
        int d = idx & 63, rest = idx >> 6;
        int h = rest & (NHQ - 1), s = rest >> 4;
        int p = pos[s];
        float c = fc[p * HD + d * 2], sn = fc[p * HD + d * 2 + 1];
        float* ptr = g_q + ((size_t)s * (NHQ * HD) + h * HD + d * 2);
        float a = ptr[0], b = ptr[1];
        ptr[0] = a * c - b * sn;
        ptr[1] = a * sn + b * c;
    } else if (idx < NQ + NK) {
        int j = idx - NQ;
        int d = j & 63, rest = j >> 6;
        int h = rest & (NKV - 1), s = rest >> 2;
        int p = pos[s];
        float c = fc[p * HD + d * 2], sn = fc[p * HD + d * 2 + 1];
        float* ptr = g_k + ((size_t)s * (NKV * HD) + h * HD + d * 2);
        float a = ptr[0], b = ptr[1];
        ptr[0] = a * c - b * sn;
        ptr[1] = a * sn + b * c;
    }
}

// ---------------------------------------------------------------------------
// Flash attention on fp16 m16n8k16. CTA = (head, 128 q-rows), 8 warps.
// Writes fp16 (half2) output directly for the O projection.
// ---------------------------------------------------------------------------
#define QS2 68
#define KS2 68
#define VS2 136
#define PS2 36
#define ATT_SMEM ((128*QS2 + 64*KS2 + 32*VS2 + 128*PS2) * 4)

__global__ __launch_bounds__(256, 1) void attn_h(uint32_t* __restrict__ outh) {
    extern __shared__ uint32_t smu[];
    uint32_t* Qs = smu;                 // [128][68]  half2
    uint32_t* Ks = Qs + 128 * QS2;      // [64][68]   half2
    uint32_t* Vp = Ks + 64 * KS2;       // [32][136]  half2 (key-pair packed)
    uint32_t* Ps = Vp + 32 * VS2;       // [128][36]  half2

    const int h   = blockIdx.x;
    const int q0  = blockIdx.y * 128;
    const int kvh = h >> 2;
    const int tid = threadIdx.x;
    const int lane = tid & 31;
    const int wq  = tid >> 5;
    const int g   = lane >> 2;
    const int tig = lane & 3;
    const int rb  = wq * 16;

    const float scale = 0.08838834764831845f;
    const float NEG = -1e30f, GUARD = -1e29f;

    // Q tile: fp32 -> fp16
#pragma unroll
    for (int i = 0; i < 16; ++i) {
        int idx = i * 256 + tid;
        int r = idx >> 5, cq = idx & 31;
        float4 v = *reinterpret_cast<const float4*>(&g_q[(size_t)(q0 + r) * (NHQ * HD) + h * HD + cq * 4]);
        uint2 o = { pack2(v.x, v.y), pack2(v.z, v.w) };
        *reinterpret_cast<uint2*>(&Qs[r * QS2 + cq * 2]) = o;
    }

    float m0 = NEG, m1 = NEG, l0 = 0.f, l1 = 0.f;
    float o[16][4];
#pragma unroll
    for (int nf = 0; nf < 16; ++nf)
#pragma unroll
        for (int f = 0; f < 4; ++f) o[nf][f] = 0.f;

    int lo = q0 - (WIN - 1); if (lo < 0) lo = 0;
    const int kb_lo = lo >> 6;
    const int kb_hi = (q0 + 127) >> 6;

    __syncthreads();

    for (int kb = kb_lo; kb <= kb_hi; ++kb) {
        const int t0 = kb * 64;
        // K tile (64x128) fp16
#pragma unroll
        for (int i = 0; i < 8; ++i) {
            int idx = i * 256 + tid;
            int r = idx >> 5, cq = idx & 31;
            float4 v = *reinterpret_cast<const float4*>(&g_k[(size_t)(t0 + r) * (NKV * HD) + kvh * HD + cq * 4]);
            uint2 ov = { pack2(v.x, v.y), pack2(v.z, v.w) };
            *reinterpret_cast<uint2*>(&Ks[r * KS2 + cq * 2]) = ov;
        }
        // V tile key-pair packed: Vp[r2][d] = half2(V[2r2][d], V[2r2+1][d])
#pragma unroll
        for (int i = 0; i < 4; ++i) {
            int idx = i * 256 + tid;
            int r2 = idx >> 5, c4 = (idx & 31) * 4;
            size_t base = (size_t)(t0 + 2 * r2) * (NKV * HD) + kvh * HD + c4;
            float4 a = *reinterpret_cast<const float4*>(&g_v[base]);
            float4 b = *reinterpret_cast<const float4*>(&g_v[base + NKV * HD]);
            uint4 ov = { pack2(a.x, b.x), pack2(a.y, b.y), pack2(a.z, b.z), pack2(a.w, b.w) };
            *reinterpret_cast<uint4*>(&Vp[r2 * VS2 + c4]) = ov;
        }
        __syncthreads();

        // ---- S = Q @ K^T (warp: 16 x 64), k16 per mma, 8 steps ----
        float s[8][4];
#pragma unroll
        for (int nf = 0; nf < 8; ++nf)
#pragma unroll
            for (int f = 0; f < 4; ++f) s[nf][f] = 0.f;

#pragma unroll
        for (int ks = 0; ks < 8; ++ks) {
            const int k2 = ks * 8;
            uint32_t a[4];
            a[0] = Qs[(rb + g) * QS2 + k2 + tig];
            a[1] = Qs[(rb + g + 8) * QS2 + k2 + tig];
            a[2] = Qs[(rb + g) * QS2 + k2 + tig + 4];
            a[3] = Qs[(rb + g + 8) * QS2 + k2 + tig + 4];
#pragma unroll
            for (int nf = 0; nf < 8; ++nf) {
                uint32_t b[2];
                b[0] = Ks[(nf * 8 + g) * KS2 + k2 + tig];
                b[1] = Ks[(nf * 8 + g) * KS2 + k2 + tig + 4];
                mma_h16(s[nf], a, b);
            }
        }

        // ---- mask + scale ----
        const int r0g = q0 + rb + g, r1g = r0g + 8;
#pragma unroll
        for (int nf = 0; nf < 8; ++nf) {
            int c0 = t0 + nf * 8 + 2 * tig;
            int c1 = c0 + 1;
            bool ok00 = (c0 <= r0g) && (r0g - c0 < WIN);
            bool ok01 = (c1 <= r0g) && (r0g - c1 < WIN);
            bool ok10 = (c0 <= r1g) && (r1g - c0 < WIN);
            bool ok11 = (c1 <= r1g) && (r1g - c1 < WIN);
            s[nf][0] = ok00 ? s[nf][0] * scale : NEG;
            s[nf][1] = ok01 ? s[nf][1] * scale : NEG;
            s[nf][2] = ok10 ? s[nf][2] * scale : NEG;
            s[nf][3] = ok11 ? s[nf][3] * scale : NEG;
        }

        // ---- online softmax ----
        float mt0 = NEG, mt1 = NEG;
#pragma unroll
        for (int nf = 0; nf < 8; ++nf) {
            mt0 = fmaxf(mt0, fmaxf(s[nf][0], s[nf][1]));
            mt1 = fmaxf(mt1, fmaxf(s[nf][2], s[nf][3]));
        }
        mt0 = fmaxf(mt0, __shfl_xor_sync(0xffffffffu, mt0, 1));
        mt0 = fmaxf(mt0, __shfl_xor_sync(0xffffffffu, mt0, 2));
        mt1 = fmaxf(mt1, __shfl_xor_sync(0xffffffffu, mt1, 1));
        mt1 = fmaxf(mt1, __shfl_xor_sync(0xffffffffu, mt1, 2));

        float mn0 = fmaxf(m0, mt0), mn1 = fmaxf(m1, mt1);
        float esc0 = (m0 > GUARD) ? __expf(m0 - mn0) : 0.f;
        float esc1 = (m1 > GUARD) ? __expf(m1 - mn1) : 0.f;

        float rs0 = 0.f, rs1 = 0.f;
#pragma unroll
        for (int nf = 0; nf < 8; ++nf) {
            float p00 = (s[nf][0] > GUARD) ? __expf(s[nf][0] - mn0) : 0.f;
            float p01 = (s[nf][1] > GUARD) ? __expf(s[nf][1] - mn0) : 0.f;
            float p10 = (s[nf][2] > GUARD) ? __expf(s[nf][2] - mn1) : 0.f;
            float p11 = (s[nf][3] > GUARD) ? __expf(s[nf][3] - mn1) : 0.f;
            rs0 += p00 + p01;
            rs1 += p10 + p11;
            Ps[(rb + g) * PS2 + nf * 4 + tig]     = pack2(p00, p01);
            Ps[(rb + g + 8) * PS2 + nf * 4 + tig] = pack2(p10, p11);
        }
        rs0 += __shfl_xor_sync(0xffffffffu, rs0, 1);
        rs0 += __shfl_xor_sync(0xffffffffu, rs0, 2);
        rs1 += __shfl_xor_sync(0xffffffffu, rs1, 1);
        rs1 += __shfl_xor_sync(0xffffffffu, rs1, 2);

        l0 = l0 * esc0 + rs0; m0 = mn0;
        l1 = l1 * esc1 + rs1; m1 = mn1;

#pragma unroll
        for (int nf = 0; nf < 16; ++nf) {
            o[nf][0] *= esc0; o[nf][1] *= esc0;
            o[nf][2] *= esc1; o[nf][3] *= esc1;
        }
        __syncwarp(0xffffffffu);

        // ---- O += P @ V (warp: 16 x 128), k16 per mma, 4 steps ----
#pragma unroll
        for (int ks = 0; ks < 4; ++ks) {
            const int k2 = ks * 8;
            uint32_t a[4];
            a[0] = Ps[(rb + g) * PS2 + k2 + tig];
            a[1] = Ps[(rb + g + 8) * PS2 + k2 + tig];
            a[2] = Ps[(rb + g) * PS2 + k2 + tig + 4];
            a[3] = Ps[(rb + g + 8) * PS2 + k2 + tig + 4];
#pragma unroll
            for (int nf = 0; nf < 16; ++nf) {
                uint32_t b[2];
                b[0] = Vp[(k2 + tig) * VS2 + nf * 8 + g];
                b[1] = Vp[(k2 + tig + 4) * VS2 + nf * 8 + g];
                mma_h16(o[nf], a, b);
            }
        }
        __syncthreads();
    }

    // ---- epilogue: fp16 half2 output (A operand of O projection) ----
    const float inv0 = 1.f / l0, inv1 = 1.f / l1;
    const int qr0 = q0 + rb + g, qr1 = qr0 + 8;
#pragma unroll
    for (int nf = 0; nf < 16; ++nf) {
        int c2 = h * (HD / 2) + nf * 4 + tig;
        outh[(size_t)qr0 * (NHQ * HD / 2) + c2] = pack2(o[nf][0] * inv0, o[nf][1] * inv0);
        outh[(size_t)qr1 * (NHQ * HD / 2) + c2] = pack2(o[nf][2] * inv1, o[nf][3] * inv1);
    }
}

// ---------------------------------------------------------------------------
extern "C" void kernel_launch(void* const* d_in, const int* in_sizes, int n_in,
                              void* d_out, int out_size) {
    const float* hs  = (const float*)d_in[0];
    const float* fc  = (const float*)d_in[1];
    const int*   pos = (const int*)d_in[4];
    const float* Wq  = (const float*)d_in[5];
    const float* Wk  = (const float*)d_in[6];
    const float* Wv  = (const float*)d_in[7];
    const float* Wo  = (const float*)d_in[8];
    float* out = (float*)d_out;

    float *qp, *kp, *vp;
    __half *hsh;
    uint32_t *attnh, *wqp, *wkp, *wvp, *wop;
    cudaGetSymbolAddress((void**)&qp,    g_q);
    cudaGetSymbolAddress((void**)&kp,    g_k);
    cudaGetSymbolAddress((void**)&vp,    g_v);
    cudaGetSymbolAddress((void**)&hsh,   g_hsh);
    cudaGetSymbolAddress((void**)&attnh, g_attnh);
    cudaGetSymbolAddress((void**)&wqp,   g_wqp);
    cudaGetSymbolAddress((void**)&wkp,   g_wkp);
    cudaGetSymbolAddress((void**)&wvp,   g_wvp);
    cudaGetSymbolAddress((void**)&wop,   g_wop);

    // fp16 conversion / packing
    {
        int n1 = S_LEN * HID;                       // 4M
        conv_half<<<n1 / (256 * 8), 256>>>(hs, hsh);
        pack_w<<<(HID / 2) * (NHQ * HD) / 4 / 256, 256>>>(Wq, wqp, NHQ * HD);
        pack_w<<<(HID / 2) * (NKV * HD) / 4 / 256, 256>>>(Wk, wkp, NKV * HD);
        pack_w<<<(HID / 2) * (NKV * HD) / 4 / 256, 256>>>(Wv, wvp, NKV * HD);
        pack_w<<<((NHQ * HD) / 2) * HID / 4 / 256, 256>>>(Wo, wop, HID);
    }

    cudaFuncSetAttribute(gemm_h, cudaFuncAttributeMaxDynamicSharedMemorySize, GEMM_SMEM);
    cudaFuncSetAttribute(attn_h, cudaFuncAttributeMaxDynamicSharedMemorySize, ATT_SMEM);

    // fused QKV projection: 8 Q-blocks + 2 K-blocks + 2 V-blocks of 256 cols
    gemm_h<<<dim3(12, 16), 256, GEMM_SMEM>>>(hsh, HID,
                                             wqp, qp, NHQ * HD, 8,
                                             wkp, kp, NKV * HD, 2,
                                             wvp, vp, NKV * HD);

    // RoPE
    {
        int total = S_LEN * NHQ * (HD / 2) + S_LEN * NKV * (HD / 2);
        rope_kernel<<<(total + 255) / 256, 256>>>(fc, pos);
    }

    // Attention (fp16 tensor-core flash) -> fp16 output
    attn_h<<<dim3(NHQ, S_LEN / 128), 256, ATT_SMEM>>>(attnh);

    // O projection
    gemm_h<<<dim3(8, 16), 256, GEMM_SMEM>>>((const __half*)attnh, NHQ * HD,
                                            wop, out, HID, 8,
                                            wop, out, HID, 0,
                                            wop, out, HID);
}

// round 9
// speedup vs baseline: 5.9239x; 1.0416x over previous
#include <cuda_runtime.h>
#include <cuda_fp16.h>
#include <cstdint>
#include <math.h>

#define S_LEN 2048
#define HID   2048
#define NHQ   16
#define NKV   4
#define HD    128
#define WIN   1024

// ---------------- scratch (no cudaMalloc allowed) ----------------
__device__ __half   g_hsh[S_LEN * HID];                // fp16 hidden state (A operand)
__device__ uint32_t g_qh[S_LEN * (NHQ * HD) / 2];      // fp16 q (rope applied), half2
__device__ uint32_t g_kh[S_LEN * (NKV * HD) / 2];      // fp16 k (rope applied), half2
__device__ uint32_t g_vh[S_LEN * (NKV * HD) / 2];      // fp16 v, half2
__device__ uint32_t g_attnh[S_LEN * (NHQ * HD) / 2];   // fp16 attention out, half2
__device__ uint32_t g_wqp[(HID / 2) * (NHQ * HD)];     // k-pair-packed fp16 weights
__device__ uint32_t g_wkp[(HID / 2) * (NKV * HD)];
__device__ uint32_t g_wvp[(HID / 2) * (NKV * HD)];
__device__ uint32_t g_wop[((NHQ * HD) / 2) * HID];

__device__ __forceinline__ uint32_t pack2(float a, float b) {
    __half2 h = __floats2half2_rn(a, b);
    return *reinterpret_cast<uint32_t*>(&h);
}
__device__ __forceinline__ void mma_h16(float c[4], const uint32_t a[4], const uint32_t b[2]) {
    asm volatile("mma.sync.aligned.m16n8k16.row.col.f32.f16.f16.f32 "
        "{%0,%1,%2,%3}, {%4,%5,%6,%7}, {%8,%9}, {%0,%1,%2,%3};"
        : "+f"(c[0]), "+f"(c[1]), "+f"(c[2]), "+f"(c[3])
        : "r"(a[0]), "r"(a[1]), "r"(a[2]), "r"(a[3]), "r"(b[0]), "r"(b[1]));
}
__device__ __forceinline__ uint32_t smem_u32(const void* p) {
    uint32_t a;
    asm("{ .reg .u64 t; cvta.to.shared.u64 t, %1; cvt.u32.u64 %0, t; }" : "=r"(a) : "l"(p));
    return a;
}
__device__ __forceinline__ void cp16(uint32_t s, const void* g) {
    asm volatile("cp.async.ca.shared.global [%0], [%1], 16;" :: "r"(s), "l"(g));
}
#define CP_COMMIT() asm volatile("cp.async.commit_group;" ::: "memory")
#define CP_WAIT1()  asm volatile("cp.async.wait_group 1;" ::: "memory")

// ---------------------------------------------------------------------------
// fp32 -> fp16 convert of hidden state; 8 elems/thread
// ---------------------------------------------------------------------------
__global__ void conv_half(const float* __restrict__ src, __half* __restrict__ dst) {
    int i = (blockIdx.x * blockDim.x + threadIdx.x) * 8;
    float4 v0 = *reinterpret_cast<const float4*>(src + i);
    float4 v1 = *reinterpret_cast<const float4*>(src + i + 4);
    uint4 o = { pack2(v0.x, v0.y), pack2(v0.z, v0.w), pack2(v1.x, v1.y), pack2(v1.z, v1.w) };
    *reinterpret_cast<uint4*>(dst + i) = o;
}

// ---------------------------------------------------------------------------
// pack all 4 weights in one launch: W[K][N] fp32 -> Wp[K/2][N] half2 pairs.
// ---------------------------------------------------------------------------
#define SEG_Q ((HID / 2) * (NHQ * HD) / 4)
#define SEG_K ((HID / 2) * (NKV * HD) / 4)
#define SEG_O (((NHQ * HD) / 2) * HID / 4)

__global__ void pack_all(const float* __restrict__ Wq, const float* __restrict__ Wk,
                         const float* __restrict__ Wv, const float* __restrict__ Wo) {
    int u = blockIdx.x * blockDim.x + threadIdx.x;
    const float* W; uint32_t* Wp; int N;
    if (u < SEG_Q)                     { W = Wq; Wp = g_wqp; N = NHQ * HD; }
    else if (u < SEG_Q + SEG_K)        { W = Wk; Wp = g_wkp; N = NKV * HD; u -= SEG_Q; }
    else if (u < SEG_Q + 2 * SEG_K)    { W = Wv; Wp = g_wvp; N = NKV * HD; u -= SEG_Q + SEG_K; }
    else                               { W = Wo; Wp = g_wop; N = HID;      u -= SEG_Q + 2 * SEG_K; }
    int nc4 = N >> 2;
    int r2 = u / nc4, c = (u % nc4) * 4;
    float4 a = *reinterpret_cast<const float4*>(&W[(size_t)(2 * r2) * N + c]);
    float4 b = *reinterpret_cast<const float4*>(&W[(size_t)(2 * r2 + 1) * N + c]);
    uint4 o = { pack2(a.x, b.x), pack2(a.y, b.y), pack2(a.z, b.z), pack2(a.w, b.w) };
    *reinterpret_cast<uint4*>(&Wp[(size_t)r2 * N + c]) = o;
}

// ---------------------------------------------------------------------------
// fp16 cp.async GEMM, CTA tile 128 x (NI*32), 8 warps (2x4), warp 64 x (NI*8),
// K-tile 32, 3 stages.
// EPI==0: fp32 output to Cout (O projection, NI=8).
// EPI==1: fused QKV: 3-way weight select, RoPE on q/k, fp16 out (NI=4).
// B smem tile: 16 kpair-rows x TN u32 (one u32 = one (col, kpair)).
// ---------------------------------------------------------------------------
#define AS2 20
#define A_U32 (128 * AS2)

template<int NI, int EPI>
__global__ __launch_bounds__(256, 1) void gemm_h(const __half* __restrict__ Ah, int K,
                                                 const uint32_t* __restrict__ Wp0, int nb0,
                                                 const uint32_t* __restrict__ Wp1, int nb1,
                                                 const uint32_t* __restrict__ Wp2,
                                                 float* __restrict__ Cout,
                                                 const float* __restrict__ fc,
                                                 const int* __restrict__ pos) {
    constexpr int TN  = NI * 32;             // tile cols
    constexpr int BS2 = TN + 8;              // u32 stride per kpair row (≡8 mod 32)
    constexpr int B_U32 = 16 * BS2;
    constexpr int STG = A_U32 + B_U32;
    constexpr int BCP = TN / 64;             // B cp16 per thread (NI=4 ->2, NI=8 ->4)

    extern __shared__ uint32_t smg[];
    const uint32_t sbase = smem_u32(smg);

    const int tid  = threadIdx.x;
    const int lane = tid & 31;
    const int wid  = tid >> 5;
    const int wm   = wid & 1;
    const int wn   = wid >> 1;
    const int g    = lane >> 2;
    const int tig  = lane & 3;
    const int brow = blockIdx.y * 128;

    const uint32_t* Wp; int N, cloc, dest = 0;
    {
        int bx = blockIdx.x;
        if (bx < nb0)            { Wp = Wp0; N = (EPI ? NHQ * HD : HID); cloc = bx * TN; dest = 0; }
        else if (bx < nb0 + nb1) { Wp = Wp1; N = NKV * HD; cloc = (bx - nb0) * TN; dest = 1; }
        else                     { Wp = Wp2; N = NKV * HD; cloc = (bx - nb0 - nb1) * TN; dest = 2; }
    }

    float acc[4][NI][4];
#pragma unroll
    for (int mi = 0; mi < 4; ++mi)
#pragma unroll
        for (int ni = 0; ni < NI; ++ni)
#pragma unroll
            for (int f = 0; f < 4; ++f) acc[mi][ni][f] = 0.f;

    const int iters = K / 32;

#define ISSUE_STAGE(st, k0)                                                          \
    do {                                                                             \
        uint32_t soff = sbase + (uint32_t)((st) * STG) * 4u;                         \
        _Pragma("unroll")                                                            \
        for (int i = 0; i < 2; ++i) {                                                \
            int idx = tid + i * 256;                                                 \
            int r = idx >> 2, ch = idx & 3;                                          \
            cp16(soff + (uint32_t)(r * AS2 * 4 + ch * 16),                           \
                 &Ah[(size_t)(brow + r) * K + (k0) + ch * 8]);                       \
        }                                                                            \
        _Pragma("unroll")                                                            \
        for (int i = 0; i < BCP; ++i) {                                              \
            int idx = tid + i * 256;                                                 \
            int r = idx / (TN / 4), ch = idx % (TN / 4);                             \
            cp16(soff + (uint32_t)(A_U32 * 4 + r * BS2 * 4 + ch * 16),               \
                 &Wp[(size_t)((k0) / 2 + r) * N + cloc + ch * 4]);                   \
        }                                                                            \
        CP_COMMIT();                                                                 \
    } while (0)

    ISSUE_STAGE(0, 0);
    ISSUE_STAGE(1, 32);

    for (int kt = 0; kt < iters; ++kt) {
        CP_WAIT1();
        __syncthreads();

        if (kt + 2 < iters) {
            ISSUE_STAGE((kt + 2) % 3, (kt + 2) * 32);
        } else {
            CP_COMMIT();
        }

        const uint32_t* As = smg + (kt % 3) * STG;
        const uint32_t* Bs = As + A_U32;

#pragma unroll
        for (int kk = 0; kk < 2; ++kk) {
            const int kb2 = kk * 8;
            uint32_t af[4][4], bf[NI][2];
#pragma unroll
            for (int mi = 0; mi < 4; ++mi) {
                int r0 = wm * 64 + mi * 16 + g;
                af[mi][0] = As[r0 * AS2 + kb2 + tig];
                af[mi][1] = As[(r0 + 8) * AS2 + kb2 + tig];
                af[mi][2] = As[r0 * AS2 + kb2 + tig + 4];
                af[mi][3] = As[(r0 + 8) * AS2 + kb2 + tig + 4];
            }
#pragma unroll
            for (int ni = 0; ni < NI; ++ni) {
                int c0 = wn * (NI * 8) + ni * 8 + g;
                bf[ni][0] = Bs[(kb2 + tig) * BS2 + c0];
                bf[ni][1] = Bs[(kb2 + tig + 4) * BS2 + c0];
            }
#pragma unroll
            for (int mi = 0; mi < 4; ++mi)
#pragma unroll
                for (int ni = 0; ni < NI; ++ni)
                    mma_h16(acc[mi][ni], af[mi], bf[ni]);
        }
        __syncthreads();
    }
#undef ISSUE_STAGE

    if (EPI == 0) {
        // fp32 output (O projection)
#pragma unroll
        for (int mi = 0; mi < 4; ++mi) {
            int r0 = brow + wm * 64 + mi * 16 + g;
#pragma unroll
            for (int ni = 0; ni < NI; ++ni) {
                int c0 = cloc + wn * (NI * 8) + ni * 8 + 2 * tig;
                float2 v0 = make_float2(acc[mi][ni][0], acc[mi][ni][1]);
                float2 v1 = make_float2(acc[mi][ni][2], acc[mi][ni][3]);
                *reinterpret_cast<float2*>(&Cout[(size_t)r0 * N + c0])       = v0;
                *reinterpret_cast<float2*>(&Cout[(size_t)(r0 + 8) * N + c0]) = v1;
            }
        }
    } else {
        // fused QKV epilogue: rope on q/k, fp16 half2 output
        uint32_t* dst = (dest == 0) ? g_qh : (dest == 1) ? g_kh : g_vh;
        const int rstr = (dest == 0) ? (NHQ * HD / 2) : (NKV * HD / 2);
#pragma unroll
        for (int mi = 0; mi < 4; ++mi) {
            int r0 = brow + wm * 64 + mi * 16 + g;
            int r1 = r0 + 8;
            int p0 = pos[r0], p1 = pos[r1];
#pragma unroll
            for (int ni = 0; ni < NI; ++ni) {
                int c0 = cloc + wn * (NI * 8) + ni * 8 + 2 * tig;  // even, global col
                float a0 = acc[mi][ni][0], b0 = acc[mi][ni][1];
                float a1 = acc[mi][ni][2], b1 = acc[mi][ni][3];
                if (dest < 2) {
                    int dcol = c0 & (HD - 1);   // 2*d within head
                    float2 cs0 = *reinterpret_cast<const float2*>(&fc[(size_t)p0 * HD + dcol]);
                    float2 cs1 = *reinterpret_cast<const float2*>(&fc[(size_t)p1 * HD + dcol]);
                    float na0 = a0 * cs0.x - b0 * cs0.y;
                    float nb0 = a0 * cs0.y + b0 * cs0.x;
                    float na1 = a1 * cs1.x - b1 * cs1.y;
                    float nb1 = a1 * cs1.y + b1 * cs1.x;
                    a0 = na0; b0 = nb0; a1 = na1; b1 = nb1;
                }
                dst[(size_t)r0 * rstr + (c0 >> 1)] = pack2(a0, b0);
                dst[(size_t)r1 * rstr + (c0 >> 1)] = pack2(a1, b1);
            }
        }
    }
}

// ---------------------------------------------------------------------------
// Flash attention on fp16 m16n8k16, consuming fp16 q/k/v directly.
// ---------------------------------------------------------------------------
#define QS2 68
#define KS2 68
#define VS2 136
#define PS2 36
#define ATT_SMEM ((128*QS2 + 64*KS2 + 32*VS2 + 128*PS2) * 4)

__global__ __launch_bounds__(256, 1) void attn_h(uint32_t* __restrict__ outh) {
    extern __shared__ uint32_t smu[];
    uint32_t* Qs = smu;                 // [128][68]
    uint32_t* Ks = Qs + 128 * QS2;      // [64][68]
    uint32_t* Vp = Ks + 64 * KS2;       // [32][136] key-pair packed
    uint32_t* Ps = Vp + 32 * VS2;       // [128][36]

    const int h   = blockIdx.x;
    const int q0  = blockIdx.y * 128;
    const int kvh = h >> 2;
    const int tid = threadIdx.x;
    const int lane = tid & 31;
    const int wq  = tid >> 5;
    const int g   = lane >> 2;
    const int tig = lane & 3;
    const int rb  = wq * 16;

    const float scale = 0.08838834764831845f;
    const float NEG = -1e30f, GUARD = -1e29f;

    // Q tile: raw u32 copy (already fp16)
#pragma unroll
    for (int i = 0; i < 8; ++i) {
        int idx = i * 256 + tid;
        int r = idx >> 4, j4 = (idx & 15) * 4;
        uint4 v = *reinterpret_cast<const uint4*>(&g_qh[(size_t)(q0 + r) * (NHQ * HD / 2) + h * (HD / 2) + j4]);
        *reinterpret_cast<uint4*>(&Qs[r * QS2 + j4]) = v;
    }

    float m0 = NEG, m1 = NEG, l0 = 0.f, l1 = 0.f;
    float o[16][4];
#pragma unroll
    for (int nf = 0; nf < 16; ++nf)
#pragma unroll
        for (int f = 0; f < 4; ++f) o[nf][f] = 0.f;

    int lo = q0 - (WIN - 1); if (lo < 0) lo = 0;
    const int kb_lo = lo >> 6;
    const int kb_hi = (q0 + 127) >> 6;

    __syncthreads();

    for (int kb = kb_lo; kb <= kb_hi; ++kb) {
        const int t0 = kb * 64;
        // K tile
#pragma unroll
        for (int i = 0; i < 4; ++i) {
            int idx = i * 256 + tid;
            int r = idx >> 4, j4 = (idx & 15) * 4;
            uint4 v = *reinterpret_cast<const uint4*>(&g_kh[(size_t)(t0 + r) * (NKV * HD / 2) + kvh * (HD / 2) + j4]);
            *reinterpret_cast<uint4*>(&Ks[r * KS2 + j4]) = v;
        }
        // V tile key-pair packed via byte_perm
#pragma unroll
        for (int i = 0; i < 8; ++i) {
            int idx = i * 256 + tid;
            int r2 = idx >> 6, j = idx & 63;
            uint32_t x = g_vh[(size_t)(t0 + 2 * r2) * (NKV * HD / 2) + kvh * (HD / 2) + j];
            uint32_t y = g_vh[(size_t)(t0 + 2 * r2 + 1) * (NKV * HD / 2) + kvh * (HD / 2) + j];
            Vp[r2 * VS2 + 2 * j]     = __byte_perm(x, y, 0x5410);
            Vp[r2 * VS2 + 2 * j + 1] = __byte_perm(x, y, 0x7632);
        }
        __syncthreads();

        // ---- S = Q @ K^T ----
        float s[8][4];
#pragma unroll
        for (int nf = 0; nf < 8; ++nf)
#pragma unroll
            for (int f = 0; f < 4; ++f) s[nf][f] = 0.f;

#pragma unroll
        for (int ks = 0; ks < 8; ++ks) {
            const int k2 = ks * 8;
            uint32_t a[4];
            a[0] = Qs[(rb + g) * QS2 + k2 + tig];
            a[1] = Qs[(rb + g + 8) * QS2 + k2 + tig];
            a[2] = Qs[(rb + g) * QS2 + k2 + tig + 4];
            a[3] = Qs[(rb + g + 8) * QS2 + k2 + tig + 4];
#pragma unroll
            for (int nf = 0; nf < 8; ++nf) {
                uint32_t b[2];
                b[0] = Ks[(nf * 8 + g) * KS2 + k2 + tig];
                b[1] = Ks[(nf * 8 + g) * KS2 + k2 + tig + 4];
                mma_h16(s[nf], a, b);
            }
        }

        // ---- mask + scale ----
        const int r0g = q0 + rb + g, r1g = r0g + 8;
#pragma unroll
        for (int nf = 0; nf < 8; ++nf) {
            int c0 = t0 + nf * 8 + 2 * tig;
            int c1 = c0 + 1;
            bool ok00 = (c0 <= r0g) && (r0g - c0 < WIN);
            bool ok01 = (c1 <= r0g) && (r0g - c1 < WIN);
            bool ok10 = (c0 <= r1g) && (r1g - c0 < WIN);
            bool ok11 = (c1 <= r1g) && (r1g - c1 < WIN);
            s[nf][0] = ok00 ? s[nf][0] * scale : NEG;
            s[nf][1] = ok01 ? s[nf][1] * scale : NEG;
            s[nf][2] = ok10 ? s[nf][2] * scale : NEG;
            s[nf][3] = ok11 ? s[nf][3] * scale : NEG;
        }

        // ---- online softmax ----
        float mt0 = NEG, mt1 = NEG;
#pragma unroll
        for (int nf = 0; nf < 8; ++nf) {
            mt0 = fmaxf(mt0, fmaxf(s[nf][0], s[nf][1]));
            mt1 = fmaxf(mt1, fmaxf(s[nf][2], s[nf][3]));
        }
        mt0 = fmaxf(mt0, __shfl_xor_sync(0xffffffffu, mt0, 1));
        mt0 = fmaxf(mt0, __shfl_xor_sync(0xffffffffu, mt0, 2));
        mt1 = fmaxf(mt1, __shfl_xor_sync(0xffffffffu, mt1, 1));
        mt1 = fmaxf(mt1, __shfl_xor_sync(0xffffffffu, mt1, 2));

        float mn0 = fmaxf(m0, mt0), mn1 = fmaxf(m1, mt1);
        float esc0 = (m0 > GUARD) ? __expf(m0 - mn0) : 0.f;
        float esc1 = (m1 > GUARD) ? __expf(m1 - mn1) : 0.f;

        float rs0 = 0.f, rs1 = 0.f;
#pragma unroll
        for (int nf = 0; nf < 8; ++nf) {
            float p00 = (s[nf][0] > GUARD) ? __expf(s[nf][0] - mn0) : 0.f;
            float p01 = (s[nf][1] > GUARD) ? __expf(s[nf][1] - mn0) : 0.f;
            float p10 = (s[nf][2] > GUARD) ? __expf(s[nf][2] - mn1) : 0.f;
            float p11 = (s[nf][3] > GUARD) ? __expf(s[nf][3] - mn1) : 0.f;
            rs0 += p00 + p01;
            rs1 += p10 + p11;
            Ps[(rb + g) * PS2 + nf * 4 + tig]     = pack2(p00, p01);
            Ps[(rb + g + 8) * PS2 + nf * 4 + tig] = pack2(p10, p11);
        }
        rs0 += __shfl_xor_sync(0xffffffffu, rs0, 1);
        rs0 += __shfl_xor_sync(0xffffffffu, rs0, 2);
        rs1 += __shfl_xor_sync(0xffffffffu, rs1, 1);
        rs1 += __shfl_xor_sync(0xffffffffu, rs1, 2);

        l0 = l0 * esc0 + rs0; m0 = mn0;
        l1 = l1 * esc1 + rs1; m1 = mn1;

#pragma unroll
        for (int nf = 0; nf < 16; ++nf) {
            o[nf][0] *= esc0; o[nf][1] *= esc0;
            o[nf][2] *= esc1; o[nf][3] *= esc1;
        }
        __syncwarp(0xffffffffu);

        // ---- O += P @ V ----
#pragma unroll
        for (int ks = 0; ks < 4; ++ks) {
            const int k2 = ks * 8;
            uint32_t a[4];
            a[0] = Ps[(rb + g) * PS2 + k2 + tig];
            a[1] = Ps[(rb + g + 8) * PS2 + k2 + tig];
            a[2] = Ps[(rb + g) * PS2 + k2 + tig + 4];
            a[3] = Ps[(rb + g + 8) * PS2 + k2 + tig + 4];
#pragma unroll
            for (int nf = 0; nf < 16; ++nf) {
                uint32_t b[2];
                b[0] = Vp[(k2 + tig) * VS2 + nf * 8 + g];
                b[1] = Vp[(k2 + tig + 4) * VS2 + nf * 8 + g];
                mma_h16(o[nf], a, b);
            }
        }
        __syncthreads();
    }

    // ---- epilogue: fp16 half2 output ----
    const float inv0 = 1.f / l0, inv1 = 1.f / l1;
    const int qr0 = q0 + rb + g, qr1 = qr0 + 8;
#pragma unroll
    for (int nf = 0; nf < 16; ++nf) {
        int c2 = h * (HD / 2) + nf * 4 + tig;
        outh[(size_t)qr0 * (NHQ * HD / 2) + c2] = pack2(o[nf][0] * inv0, o[nf][1] * inv0);
        outh[(size_t)qr1 * (NHQ * HD / 2) + c2] = pack2(o[nf][2] * inv1, o[nf][3] * inv1);
    }
}

// ---------------------------------------------------------------------------
extern "C" void kernel_launch(void* const* d_in, const int* in_sizes, int n_in,
                              void* d_out, int out_size) {
    const float* hs  = (const float*)d_in[0];
    const float* fc  = (const float*)d_in[1];
    const int*   pos = (const int*)d_in[4];
    const float* Wq  = (const float*)d_in[5];
    const float* Wk  = (const float*)d_in[6];
    const float* Wv  = (const float*)d_in[7];
    const float* Wo  = (const float*)d_in[8];
    float* out = (float*)d_out;

    __half *hsh;
    uint32_t *attnh, *wqp, *wkp, *wvp, *wop;
    cudaGetSymbolAddress((void**)&hsh,   g_hsh);
    cudaGetSymbolAddress((void**)&attnh, g_attnh);
    cudaGetSymbolAddress((void**)&wqp,   g_wqp);
    cudaGetSymbolAddress((void**)&wkp,   g_wkp);
    cudaGetSymbolAddress((void**)&wvp,   g_wvp);
    cudaGetSymbolAddress((void**)&wop,   g_wop);

    // fp16 conversion / packing (2 launches)
    conv_half<<<(S_LEN * HID) / (256 * 8), 256>>>(hs, hsh);
    pack_all<<<(SEG_Q + 2 * SEG_K + SEG_O) / 256, 256>>>(Wq, Wk, Wv, Wo);

    // smem: 3 stages of (A: 128x20 u32, B: 16 x (TN+8) u32)
    constexpr int SMEM_QKV = 3 * (A_U32 + 16 * (128 + 8)) * 4;   // NI=4 -> 56832 B
    constexpr int SMEM_O   = 3 * (A_U32 + 16 * (256 + 8)) * 4;   // NI=8 -> 81408 B
    cudaFuncSetAttribute((const void*)gemm_h<4, 1>, cudaFuncAttributeMaxDynamicSharedMemorySize, SMEM_QKV);
    cudaFuncSetAttribute((const void*)gemm_h<8, 0>, cudaFuncAttributeMaxDynamicSharedMemorySize, SMEM_O);
    cudaFuncSetAttribute((const void*)attn_h, cudaFuncAttributeMaxDynamicSharedMemorySize, ATT_SMEM);

    // fused QKV + RoPE: 128x128 tiles, 24 col blocks (16 Q + 4 K + 4 V) x 16 rows
    gemm_h<4, 1><<<dim3(24, 16), 256, SMEM_QKV>>>(hsh, HID, wqp, 16, wkp, 4, wvp,
                                                  nullptr, fc, pos);

    // attention (fp16 tensor-core flash)
    attn_h<<<dim3(NHQ, S_LEN / 128), 256, ATT_SMEM>>>(attnh);

    // O projection: 128x256 tiles, 8x16 = 128 CTAs
    gemm_h<8, 0><<<dim3(8, 16), 256, SMEM_O>>>((const __half*)attnh, NHQ * HD, wop, 8,
                                               nullptr, 0, nullptr, out, nullptr, nullptr);
}